// round 2
// baseline (speedup 1.0000x reference)
#include <cuda_runtime.h>
#include <cstdint>
#include <cstddef>

// Problem constants
#define BSZ 4096
#define TSZ 100
#define FSZ 13
#define HSZ 100
#define G4  400          // 4*H
#define KPX 16           // padded x k-dim (13 -> 16)
#define WPX 20           // row stride (floats) of padded W_ih0 in smem (conflict-free)
#define BR  28           // batch rows per CTA
#define RPT 7            // rows per thread
#define NTHREADS 512     // 4 row-groups x 128 col-threads

// ---------------------------------------------------------------------------
// Scratch (device globals; no runtime allocation allowed)
// ---------------------------------------------------------------------------
__device__ float g_h0seq[(size_t)BSZ * TSZ * HSZ];   // 163.84 MB  [b][t][h]
__device__ float g_zx1[(size_t)BSZ * TSZ * G4];      // 655.36 MB  [b*T+t][4H] (includes bias1)

// ---------------------------------------------------------------------------
// Helpers
// ---------------------------------------------------------------------------
__device__ __forceinline__ float sigf(float x) {
    // 1/(1+e^-x); exp overflow -> denom inf -> 0, fine.
    return __fdividef(1.f, 1.f + __expf(-x));
}
__device__ __forceinline__ float tanhfast(float x) {
    float t = fminf(fmaxf(2.f * x, -30.f), 30.f);
    float e = __expf(t);
    return __fdividef(e - 1.f, e + 1.f);
}
// packed fp32x2 fma: d.lo += a.lo*b.lo ; d.hi += a.hi*b.hi
__device__ __forceinline__ void ffma2(unsigned long long &d,
                                      unsigned long long a,
                                      unsigned long long b) {
    asm("fma.rn.f32x2 %0, %1, %2, %0;" : "+l"(d) : "l"(a), "l"(b));
}
__device__ __forceinline__ unsigned long long pk(float lo, float hi) {
    unsigned long long r;
    asm("mov.b64 %0, {%1, %2};" : "=l"(r) : "f"(lo), "f"(hi));
    return r;
}
__device__ __forceinline__ float psum(unsigned long long a) {
    float lo = __uint_as_float((unsigned)(a & 0xffffffffull));
    float hi = __uint_as_float((unsigned)(a >> 32));
    return lo + hi;
}
__device__ __forceinline__ ulonglong2 ld2(const float* p) {
    return *reinterpret_cast<const ulonglong2*>(p);
}

// ===========================================================================
// Kernel A: layer-0 recurrence (fused x @ W_ih0^T), writes h0_seq
// smem: W_hh0[400][100] | W_ih0p[400][20] | bias0[400] | h0[28][100] | xs[28][16]
// ===========================================================================
__global__ void __launch_bounds__(NTHREADS, 1)
k_layer0(const float* __restrict__ x, const int* __restrict__ lengths,
         const float* __restrict__ Wih0, const float* __restrict__ Whh0,
         const float* __restrict__ bih0, const float* __restrict__ bhh0)
{
    extern __shared__ float sm[];
    float* sWhh = sm;                     // 40000
    float* sWih = sWhh + 40000;           // 8000 (400*20)
    float* sB   = sWih + 8000;            // 400
    float* sH   = sB   + 400;             // 2800
    float* sX   = sH   + 2800;            // 448

    const int tid = threadIdx.x;
    for (int i = tid; i < 40000; i += NTHREADS) sWhh[i] = Whh0[i];
    for (int i = tid; i < 8000;  i += NTHREADS) {
        int j = i / WPX, kk = i % WPX;
        sWih[i] = (kk < FSZ) ? Wih0[j * FSZ + kk] : 0.f;
    }
    for (int i = tid; i < G4; i += NTHREADS) sB[i] = bih0[i] + bhh0[i];
    for (int i = tid; i < BR * HSZ; i += NTHREADS) sH[i] = 0.f;

    const int u   = tid & 127;
    const int yg  = tid >> 7;
    const bool act = (u < HSZ);
    const int r0  = yg * RPT;
    const int grow0 = blockIdx.x * BR;

    float c[RPT];
    int   len[RPT];
    bool  rv[RPT];
    #pragma unroll
    for (int r = 0; r < RPT; r++) {
        int grow = grow0 + r0 + r;
        rv[r]  = (grow < BSZ);
        len[r] = rv[r] ? lengths[grow] : 0;
        c[r]   = 0.f;
    }

    __syncthreads();
    float bi = 0.f, bf = 0.f, bg = 0.f, bo = 0.f;
    if (act) { bi = sB[u]; bf = sB[u + 100]; bg = sB[u + 200]; bo = sB[u + 300]; }

    #pragma unroll 1
    for (int t = 0; t < TSZ; t++) {
        // stage x_t (28 rows x 16 padded cols)
        if (tid < BR * KPX) {
            int r = tid >> 4, kk = tid & 15;
            int grow = grow0 + r;
            sX[tid] = (kk < FSZ && grow < BSZ)
                      ? x[(size_t)grow * (TSZ * FSZ) + t * FSZ + kk] : 0.f;
        }
        __syncthreads();

        unsigned long long acc[RPT][4];
        if (act) {
            #pragma unroll
            for (int r = 0; r < RPT; r++) {
                acc[r][0] = pk(bi, 0.f); acc[r][1] = pk(bf, 0.f);
                acc[r][2] = pk(bg, 0.f); acc[r][3] = pk(bo, 0.f);
            }
            // x part (k = 0..15, zero padded)
            #pragma unroll
            for (int kc = 0; kc < KPX; kc += 4) {
                ulonglong2 h2[RPT];
                #pragma unroll
                for (int r = 0; r < RPT; r++) h2[r] = ld2(&sX[(r0 + r) * KPX + kc]);
                #pragma unroll
                for (int g = 0; g < 4; g++) {
                    ulonglong2 w2 = ld2(&sWih[(g * 100 + u) * WPX + kc]);
                    #pragma unroll
                    for (int r = 0; r < RPT; r++) {
                        ffma2(acc[r][g], w2.x, h2[r].x);
                        ffma2(acc[r][g], w2.y, h2[r].y);
                    }
                }
            }
            // h part (k = 0..99)
            #pragma unroll 5
            for (int kc = 0; kc < HSZ; kc += 4) {
                ulonglong2 h2[RPT];
                #pragma unroll
                for (int r = 0; r < RPT; r++) h2[r] = ld2(&sH[(r0 + r) * HSZ + kc]);
                #pragma unroll
                for (int g = 0; g < 4; g++) {
                    ulonglong2 w2 = ld2(&sWhh[(g * 100 + u) * HSZ + kc]);
                    #pragma unroll
                    for (int r = 0; r < RPT; r++) {
                        ffma2(acc[r][g], w2.x, h2[r].x);
                        ffma2(acc[r][g], w2.y, h2[r].y);
                    }
                }
            }
        }
        __syncthreads();   // all reads of sH for step t complete

        if (act) {
            #pragma unroll
            for (int r = 0; r < RPT; r++) {
                float zi = psum(acc[r][0]);
                float zf = psum(acc[r][1]);
                float zg = psum(acc[r][2]);
                float zo = psum(acc[r][3]);
                float cn = sigf(zf) * c[r] + sigf(zi) * tanhfast(zg);
                float hn = sigf(zo) * tanhfast(cn);
                bool upd = (t < len[r]);
                if (upd) {
                    c[r] = cn;
                    sH[(r0 + r) * HSZ + u] = hn;
                }
                if (rv[r]) {
                    int grow = grow0 + r0 + r;
                    g_h0seq[((size_t)grow * TSZ + t) * HSZ + u] = sH[(r0 + r) * HSZ + u];
                }
            }
        }
        __syncthreads();
    }
}

// ===========================================================================
// Kernel G: Zx1[m][j] = h0_seq[m] @ W_ih1^T + (b_ih1 + b_hh1)   (pure GEMM)
// smem: W_ih1[400][100] | bias1[400] | hbuf[28][100]
// ===========================================================================
__global__ void __launch_bounds__(NTHREADS, 1)
k_ingemm1(const float* __restrict__ Wih1,
          const float* __restrict__ bih1, const float* __restrict__ bhh1)
{
    extern __shared__ float sm[];
    float* sW  = sm;           // 40000
    float* sB  = sW + 40000;   // 400
    float* sHb = sB + 400;     // 2800

    const int tid = threadIdx.x;
    for (int i = tid; i < 40000; i += NTHREADS) sW[i] = Wih1[i];
    for (int i = tid; i < G4; i += NTHREADS) sB[i] = bih1[i] + bhh1[i];
    __syncthreads();

    const int u  = tid & 127;
    const int yg = tid >> 7;
    const bool act = (u < HSZ);
    const int r0 = yg * RPT;

    float bi = 0.f, bf = 0.f, bg = 0.f, bo = 0.f;
    if (act) { bi = sB[u]; bf = sB[u + 100]; bg = sB[u + 200]; bo = sB[u + 300]; }

    const size_t Mtot = (size_t)BSZ * TSZ;              // 409600
    const int NT = (int)((Mtot + BR - 1) / BR);          // 14629

    #pragma unroll 1
    for (int tile = blockIdx.x; tile < NT; tile += gridDim.x) {
        size_t m0 = (size_t)tile * BR;
        __syncthreads();   // previous tile's reads done before overwrite
        {
            size_t base = m0 * HSZ;
            for (int i = tid; i < BR * HSZ; i += NTHREADS) {
                size_t idx = base + i;
                sHb[i] = (idx < Mtot * HSZ) ? g_h0seq[idx] : 0.f;
            }
        }
        __syncthreads();

        if (act) {
            unsigned long long acc[RPT][4];
            #pragma unroll
            for (int r = 0; r < RPT; r++) {
                acc[r][0] = pk(bi, 0.f); acc[r][1] = pk(bf, 0.f);
                acc[r][2] = pk(bg, 0.f); acc[r][3] = pk(bo, 0.f);
            }
            #pragma unroll 5
            for (int kc = 0; kc < HSZ; kc += 4) {
                ulonglong2 h2[RPT];
                #pragma unroll
                for (int r = 0; r < RPT; r++) h2[r] = ld2(&sHb[(r0 + r) * HSZ + kc]);
                #pragma unroll
                for (int g = 0; g < 4; g++) {
                    ulonglong2 w2 = ld2(&sW[(g * 100 + u) * HSZ + kc]);
                    #pragma unroll
                    for (int r = 0; r < RPT; r++) {
                        ffma2(acc[r][g], w2.x, h2[r].x);
                        ffma2(acc[r][g], w2.y, h2[r].y);
                    }
                }
            }
            #pragma unroll
            for (int r = 0; r < RPT; r++) {
                size_t m = m0 + r0 + r;
                if (m < Mtot) {
                    #pragma unroll
                    for (int g = 0; g < 4; g++)
                        g_zx1[m * G4 + g * 100 + u] = psum(acc[r][g]);
                }
            }
        }
    }
}

// ===========================================================================
// Kernel B: layer-1 recurrence consuming Zx1; epilogue: out = h1 @ W_fc^T + b
// smem: W_hh1[400][100] | h1[28][100] | wfc[128]
// ===========================================================================
__global__ void __launch_bounds__(NTHREADS, 1)
k_layer1(const int* __restrict__ lengths, const float* __restrict__ Whh1,
         const float* __restrict__ Wfc, const float* __restrict__ bfc,
         float* __restrict__ out)
{
    extern __shared__ float sm[];
    float* sW   = sm;            // 40000
    float* sH   = sW + 40000;    // 2800
    float* sWfc = sH + 2800;     // 128

    const int tid = threadIdx.x;
    for (int i = tid; i < 40000; i += NTHREADS) sW[i] = Whh1[i];
    for (int i = tid; i < BR * HSZ; i += NTHREADS) sH[i] = 0.f;
    if (tid < 128) sWfc[tid] = (tid < HSZ) ? Wfc[tid] : 0.f;

    const int u  = tid & 127;
    const int yg = tid >> 7;
    const bool act = (u < HSZ);
    const int r0 = yg * RPT;
    const int grow0 = blockIdx.x * BR;

    float c[RPT];
    int   len[RPT];
    bool  rv[RPT];
    #pragma unroll
    for (int r = 0; r < RPT; r++) {
        int grow = grow0 + r0 + r;
        rv[r]  = (grow < BSZ);
        len[r] = rv[r] ? lengths[grow] : 0;
        c[r]   = 0.f;
    }
    __syncthreads();

    #pragma unroll 1
    for (int t = 0; t < TSZ; t++) {
        unsigned long long acc[RPT][4];
        if (act) {
            #pragma unroll
            for (int r = 0; r < RPT; r++) {
                int grow = grow0 + r0 + r;
                size_t zb = ((size_t)grow * TSZ + t) * G4;
                #pragma unroll
                for (int g = 0; g < 4; g++) {
                    float zin = rv[r] ? g_zx1[zb + g * 100 + u] : 0.f;
                    acc[r][g] = pk(zin, 0.f);
                }
            }
            #pragma unroll 5
            for (int kc = 0; kc < HSZ; kc += 4) {
                ulonglong2 h2[RPT];
                #pragma unroll
                for (int r = 0; r < RPT; r++) h2[r] = ld2(&sH[(r0 + r) * HSZ + kc]);
                #pragma unroll
                for (int g = 0; g < 4; g++) {
                    ulonglong2 w2 = ld2(&sW[(g * 100 + u) * HSZ + kc]);
                    #pragma unroll
                    for (int r = 0; r < RPT; r++) {
                        ffma2(acc[r][g], w2.x, h2[r].x);
                        ffma2(acc[r][g], w2.y, h2[r].y);
                    }
                }
            }
        }
        __syncthreads();   // all reads of sH done

        if (act) {
            #pragma unroll
            for (int r = 0; r < RPT; r++) {
                float zi = psum(acc[r][0]);
                float zf = psum(acc[r][1]);
                float zg = psum(acc[r][2]);
                float zo = psum(acc[r][3]);
                float cn = sigf(zf) * c[r] + sigf(zi) * tanhfast(zg);
                float hn = sigf(zo) * tanhfast(cn);
                if (t < len[r]) {
                    c[r] = cn;
                    sH[(r0 + r) * HSZ + u] = hn;
                }
            }
        }
        __syncthreads();
    }

    // epilogue: out[row] = dot(h1[row], Wfc) + b_fc
    if (tid < BR) {
        int grow = grow0 + tid;
        if (grow < BSZ) {
            float s = bfc[0];
            #pragma unroll 10
            for (int k = 0; k < HSZ; k++) s += sH[tid * HSZ + k] * sWfc[k];
            out[grow] = s;
        }
    }
}

// ===========================================================================
// Launch
// ===========================================================================
extern "C" void kernel_launch(void* const* d_in, const int* in_sizes, int n_in,
                              void* d_out, int out_size)
{
    const float* x       = (const float*)d_in[0];
    const int*   lengths = (const int*)  d_in[1];
    const float* Wih0    = (const float*)d_in[2];
    const float* Whh0    = (const float*)d_in[3];
    const float* bih0    = (const float*)d_in[4];
    const float* bhh0    = (const float*)d_in[5];
    const float* Wih1    = (const float*)d_in[6];
    const float* Whh1    = (const float*)d_in[7];
    const float* bih1    = (const float*)d_in[8];
    const float* bhh1    = (const float*)d_in[9];
    const float* Wfc     = (const float*)d_in[10];
    const float* bfc     = (const float*)d_in[11];
    float* out = (float*)d_out;

    const int smA = (40000 + 8000 + 400 + 2800 + 448) * 4;  // 206,592 B
    const int smG = (40000 + 400 + 2800) * 4;               // 172,800 B
    const int smB = (40000 + 2800 + 128) * 4;               // 171,712 B

    cudaFuncSetAttribute(k_layer0,  cudaFuncAttributeMaxDynamicSharedMemorySize, smA);
    cudaFuncSetAttribute(k_ingemm1, cudaFuncAttributeMaxDynamicSharedMemorySize, smG);
    cudaFuncSetAttribute(k_layer1,  cudaFuncAttributeMaxDynamicSharedMemorySize, smB);

    const int gridA = (BSZ + BR - 1) / BR;   // 147
    k_layer0 <<<gridA, NTHREADS, smA>>>(x, lengths, Wih0, Whh0, bih0, bhh0);
    k_ingemm1<<<148,   NTHREADS, smG>>>(Wih1, bih1, bhh1);
    k_layer1 <<<gridA, NTHREADS, smB>>>(lengths, Whh1, Wfc, bfc, out);
}

// round 3
// speedup vs baseline: 1.3422x; 1.3422x over previous
#include <cuda_runtime.h>
#include <cstdint>
#include <cstddef>

// Problem constants
#define BSZ 4096
#define TSZ 100
#define FSZ 13
#define HSZ 100
#define G4  400
#define KPX 16           // padded x k-dim
#define WPX 20           // padded W_ih0 row stride (conflict-free)
#define BR  30           // batch rows per CTA (recurrent kernels)
#define RPT 6            // rows per thread (5 groups x 100 lanes)
#define NTHREADS 512
#define BRG 25           // rows per tile in input GEMM (len-skippable chunks)
#define RPTG 5
#define NITEMS (BSZ*4)   // (grow, chunk) items for input GEMM

// ---------------------------------------------------------------------------
// Scratch (device globals, zero-initialized at module load)
// ---------------------------------------------------------------------------
__device__ float g_h0seq[(size_t)BSZ * TSZ * HSZ];   // [b][t][h]; only t<len written
__device__ float g_zx1[(size_t)BSZ * TSZ * G4];      // [b*T+t][4H]

// ---------------------------------------------------------------------------
// Helpers
// ---------------------------------------------------------------------------
__device__ __forceinline__ float sigf(float x) {
    return __fdividef(1.f, 1.f + __expf(-x));
}
__device__ __forceinline__ float tanhfast(float x) {
    float t = fminf(fmaxf(2.f * x, -30.f), 30.f);
    float e = __expf(t);
    return __fdividef(e - 1.f, e + 1.f);
}
__device__ __forceinline__ void ffma2(unsigned long long &d,
                                      unsigned long long a,
                                      unsigned long long b) {
    asm("fma.rn.f32x2 %0, %1, %2, %0;" : "+l"(d) : "l"(a), "l"(b));
}
__device__ __forceinline__ unsigned long long pk(float lo, float hi) {
    unsigned long long r;
    asm("mov.b64 %0, {%1, %2};" : "=l"(r) : "f"(lo), "f"(hi));
    return r;
}
__device__ __forceinline__ float psum(unsigned long long a) {
    float lo = __uint_as_float((unsigned)(a & 0xffffffffull));
    float hi = __uint_as_float((unsigned)(a >> 32));
    return lo + hi;
}
__device__ __forceinline__ ulonglong2 ld2(const float* p) {
    return *reinterpret_cast<const ulonglong2*>(p);
}

// ===========================================================================
// Kernel A: layer-0 recurrence, writes h0_seq (only t < len)
// ===========================================================================
__global__ void __launch_bounds__(NTHREADS, 1)
k_layer0(const float* __restrict__ x, const int* __restrict__ lengths,
         const float* __restrict__ Wih0, const float* __restrict__ Whh0,
         const float* __restrict__ bih0, const float* __restrict__ bhh0)
{
    extern __shared__ float sm[];
    float* sWhh = sm;                    // 40000
    float* sWih = sWhh + 40000;          // 8000 (400 x 20)
    float* sB   = sWih + 8000;           // 400
    float* sH   = sB   + 400;            // 2 x 3000 (double buffer)
    float* sX   = sH   + 6000;           // 2 x 480
    int*   sLen = (int*)(sX + 960);      // 32

    const int tid = threadIdx.x;
    const int grow0 = blockIdx.x * BR;

    for (int i = tid; i < 40000; i += NTHREADS) sWhh[i] = Whh0[i];
    for (int i = tid; i < 8000;  i += NTHREADS) {
        int j = i / WPX, kk = i % WPX;
        sWih[i] = (kk < FSZ) ? Wih0[j * FSZ + kk] : 0.f;
    }
    for (int i = tid; i < G4; i += NTHREADS) sB[i] = bih0[i] + bhh0[i];
    for (int i = tid; i < 2 * BR * HSZ; i += NTHREADS) sH[i] = 0.f;
    if (tid < 32) {
        int g = grow0 + tid;
        sLen[tid] = (tid < BR && g < BSZ) ? lengths[g] : 0;
    }
    // stage x(t=0) into sX[0]
    if (tid < BR * KPX) {
        int r = tid >> 4, kk = tid & 15;
        int g = grow0 + r;
        sX[tid] = (kk < FSZ && g < BSZ) ? x[(size_t)g * (TSZ * FSZ) + kk] : 0.f;
    }
    __syncthreads();

    const int u  = tid % HSZ;
    const int yg = tid / HSZ;
    const bool act = (tid < 500);
    const int r0 = yg * RPT;

    int Lmax = 0;
    #pragma unroll
    for (int r = 0; r < BR; r++) Lmax = max(Lmax, sLen[r]);

    float c[RPT], hreg[RPT]; int len[RPT];
    #pragma unroll
    for (int r = 0; r < RPT; r++) {
        c[r] = 0.f; hreg[r] = 0.f;
        len[r] = act ? sLen[r0 + r] : 0;
    }
    float bi = 0.f, bf = 0.f, bg_ = 0.f, bo = 0.f;
    if (act) { bi = sB[u]; bf = sB[u + 100]; bg_ = sB[u + 200]; bo = sB[u + 300]; }

    int p = 0;
    #pragma unroll 1
    for (int t = 0; t < Lmax; t++) {
        // prefetch x(t+1) into regs (overlaps compute)
        float xs = 0.f;
        const bool st = (tid < BR * KPX) && (t + 1 < Lmax);
        if (st) {
            int r = tid >> 4, kk = tid & 15;
            int g = grow0 + r;
            xs = (kk < FSZ && g < BSZ)
               ? x[(size_t)g * (TSZ * FSZ) + (t + 1) * FSZ + kk] : 0.f;
        }

        unsigned long long acc[RPT][4];
        if (act) {
            #pragma unroll
            for (int r = 0; r < RPT; r++) {
                acc[r][0] = pk(bi, 0.f); acc[r][1] = pk(bf, 0.f);
                acc[r][2] = pk(bg_, 0.f); acc[r][3] = pk(bo, 0.f);
            }
            const float* hb = sH + p * BR * HSZ;
            const float* xb = sX + p * BR * KPX;
            #pragma unroll
            for (int kc = 0; kc < KPX; kc += 4) {
                ulonglong2 h2[RPT];
                #pragma unroll
                for (int r = 0; r < RPT; r++) h2[r] = ld2(&xb[(r0 + r) * KPX + kc]);
                #pragma unroll
                for (int g = 0; g < 4; g++) {
                    ulonglong2 w2 = ld2(&sWih[(g * HSZ + u) * WPX + kc]);
                    #pragma unroll
                    for (int r = 0; r < RPT; r++) {
                        ffma2(acc[r][g], w2.x, h2[r].x);
                        ffma2(acc[r][g], w2.y, h2[r].y);
                    }
                }
            }
            #pragma unroll 5
            for (int kc = 0; kc < HSZ; kc += 4) {
                ulonglong2 h2[RPT];
                #pragma unroll
                for (int r = 0; r < RPT; r++) h2[r] = ld2(&hb[(r0 + r) * HSZ + kc]);
                #pragma unroll
                for (int g = 0; g < 4; g++) {
                    ulonglong2 w2 = ld2(&sWhh[(g * HSZ + u) * HSZ + kc]);
                    #pragma unroll
                    for (int r = 0; r < RPT; r++) {
                        ffma2(acc[r][g], w2.x, h2[r].x);
                        ffma2(acc[r][g], w2.y, h2[r].y);
                    }
                }
            }
        }
        if (st) sX[(1 - p) * BR * KPX + tid] = xs;

        if (act) {
            float* hnb = sH + (1 - p) * BR * HSZ;
            #pragma unroll
            for (int r = 0; r < RPT; r++) {
                float zi = psum(acc[r][0]);
                float zf = psum(acc[r][1]);
                float zg = psum(acc[r][2]);
                float zo = psum(acc[r][3]);
                float cn = sigf(zf) * c[r] + sigf(zi) * tanhfast(zg);
                float hn = sigf(zo) * tanhfast(cn);
                if (t < len[r]) {
                    c[r] = cn; hreg[r] = hn;
                    g_h0seq[((size_t)(grow0 + r0 + r) * TSZ + t) * HSZ + u] = hn;
                }
                hnb[(r0 + r) * HSZ + u] = hreg[r];
            }
        }
        __syncthreads();
        p ^= 1;
    }
}

// ===========================================================================
// Kernel G: Zx1 = h0_seq @ W_ih1^T + bias1 ; chunk-skipped by lengths
// ===========================================================================
__global__ void __launch_bounds__(NTHREADS, 1)
k_ingemm1(const float* __restrict__ Wih1, const int* __restrict__ lengths,
          const float* __restrict__ bih1, const float* __restrict__ bhh1)
{
    extern __shared__ float sm[];
    float* sW  = sm;                     // 40000
    float* sB  = sW + 40000;             // 400
    float* sHb = sB + 400;               // 2 x 2500 (double buffer)
    int*   sLen = (int*)(sHb + 5000);    // 4096

    const int tid = threadIdx.x;
    for (int i = tid; i < 40000; i += NTHREADS) sW[i] = Wih1[i];
    for (int i = tid; i < G4; i += NTHREADS) sB[i] = bih1[i] + bhh1[i];
    for (int i = tid; i < BSZ; i += NTHREADS) sLen[i] = lengths[i];
    __syncthreads();

    const int u  = tid % HSZ;
    const int yg = tid / HSZ;
    const bool act = (tid < 500);
    const int r0 = yg * RPTG;
    float bi = 0.f, bf = 0.f, bg_ = 0.f, bo = 0.f;
    if (act) { bi = sB[u]; bf = sB[u + 100]; bg_ = sB[u + 200]; bo = sB[u + 300]; }

    const int stride = gridDim.x;
    int i = blockIdx.x;
    while (i < NITEMS && (i & 3) * BRG >= sLen[i >> 2]) i += stride;

    if (i < NITEMS) {
        const float4* src = (const float4*)(g_h0seq +
            ((size_t)(i >> 2) * TSZ + (i & 3) * BRG) * HSZ);
        for (int j = tid; j < BRG * HSZ / 4; j += NTHREADS)
            ((float4*)sHb)[j] = src[j];
    }
    __syncthreads();

    int p = 0;
    #pragma unroll 1
    while (i < NITEMS) {
        int inext = i + stride;
        while (inext < NITEMS && (inext & 3) * BRG >= sLen[inext >> 2]) inext += stride;

        // prefetch next tile into regs
        float4 pf0, pf1; bool hp0 = false, hp1 = false;
        if (inext < NITEMS) {
            const float4* src = (const float4*)(g_h0seq +
                ((size_t)(inext >> 2) * TSZ + (inext & 3) * BRG) * HSZ);
            if (tid < BRG * HSZ / 4)        { pf0 = src[tid];       hp0 = true; }
            if (tid + 512 < BRG * HSZ / 4)  { pf1 = src[tid + 512]; hp1 = true; }
        }

        if (act) {
            unsigned long long acc[RPTG][4];
            #pragma unroll
            for (int r = 0; r < RPTG; r++) {
                acc[r][0] = pk(bi, 0.f); acc[r][1] = pk(bf, 0.f);
                acc[r][2] = pk(bg_, 0.f); acc[r][3] = pk(bo, 0.f);
            }
            const float* hb = sHb + p * BRG * HSZ;
            #pragma unroll 5
            for (int kc = 0; kc < HSZ; kc += 4) {
                ulonglong2 h2[RPTG];
                #pragma unroll
                for (int r = 0; r < RPTG; r++) h2[r] = ld2(&hb[(r0 + r) * HSZ + kc]);
                #pragma unroll
                for (int g = 0; g < 4; g++) {
                    ulonglong2 w2 = ld2(&sW[(g * HSZ + u) * HSZ + kc]);
                    #pragma unroll
                    for (int r = 0; r < RPTG; r++) {
                        ffma2(acc[r][g], w2.x, h2[r].x);
                        ffma2(acc[r][g], w2.y, h2[r].y);
                    }
                }
            }
            size_t mbase = (size_t)(i >> 2) * TSZ + (i & 3) * BRG + r0;
            #pragma unroll
            for (int r = 0; r < RPTG; r++) {
                size_t m = mbase + r;
                #pragma unroll
                for (int g = 0; g < 4; g++)
                    g_zx1[m * G4 + g * HSZ + u] = psum(acc[r][g]);
            }
        }
        float* dst = sHb + (1 - p) * BRG * HSZ;
        if (hp0) ((float4*)dst)[tid] = pf0;
        if (hp1) ((float4*)dst)[tid + 512] = pf1;
        __syncthreads();
        i = inext; p ^= 1;
    }
}

// ===========================================================================
// Kernel B: layer-1 recurrence + fc epilogue
// ===========================================================================
__global__ void __launch_bounds__(NTHREADS, 1)
k_layer1(const int* __restrict__ lengths, const float* __restrict__ Whh1,
         const float* __restrict__ Wfc, const float* __restrict__ bfc,
         float* __restrict__ out)
{
    extern __shared__ float sm[];
    float* sW   = sm;                    // 40000
    float* sH   = sW + 40000;            // 2 x 3000
    float* sWfc = sH + 6000;             // 128
    int*   sLen = (int*)(sWfc + 128);    // 32

    const int tid = threadIdx.x;
    const int grow0 = blockIdx.x * BR;
    for (int i = tid; i < 40000; i += NTHREADS) sW[i] = Whh1[i];
    for (int i = tid; i < 2 * BR * HSZ; i += NTHREADS) sH[i] = 0.f;
    if (tid < 128) sWfc[tid] = (tid < HSZ) ? Wfc[tid] : 0.f;
    if (tid < 32) {
        int g = grow0 + tid;
        sLen[tid] = (tid < BR && g < BSZ) ? lengths[g] : 0;
    }
    __syncthreads();

    const int u  = tid % HSZ;
    const int yg = tid / HSZ;
    const bool act = (tid < 500);
    const int r0 = yg * RPT;

    int Lmax = 0;
    #pragma unroll
    for (int r = 0; r < BR; r++) Lmax = max(Lmax, sLen[r]);

    float c[RPT], hreg[RPT]; int len[RPT]; bool rv[RPT];
    #pragma unroll
    for (int r = 0; r < RPT; r++) {
        c[r] = 0.f; hreg[r] = 0.f;
        len[r] = act ? sLen[r0 + r] : 0;
        rv[r]  = act && (grow0 + r0 + r < BSZ);
    }

    // prologue: prefetch z(0)
    float zn[RPT][4];
    #pragma unroll
    for (int r = 0; r < RPT; r++) {
        size_t zb = ((size_t)(grow0 + r0 + r) * TSZ) * G4;
        #pragma unroll
        for (int g = 0; g < 4; g++)
            zn[r][g] = rv[r] ? g_zx1[zb + g * HSZ + u] : 0.f;
    }

    int p = 0;
    #pragma unroll 1
    for (int t = 0; t < Lmax; t++) {
        unsigned long long acc[RPT][4];
        if (act) {
            #pragma unroll
            for (int r = 0; r < RPT; r++)
                #pragma unroll
                for (int g = 0; g < 4; g++) acc[r][g] = pk(zn[r][g], 0.f);
        }
        // prefetch z(t+1), overlapping the k-loop
        if (t + 1 < Lmax) {
            #pragma unroll
            for (int r = 0; r < RPT; r++) {
                size_t zb = ((size_t)(grow0 + r0 + r) * TSZ + (t + 1)) * G4;
                #pragma unroll
                for (int g = 0; g < 4; g++)
                    zn[r][g] = rv[r] ? g_zx1[zb + g * HSZ + u] : 0.f;
            }
        }
        if (act) {
            const float* hb = sH + p * BR * HSZ;
            #pragma unroll 5
            for (int kc = 0; kc < HSZ; kc += 4) {
                ulonglong2 h2[RPT];
                #pragma unroll
                for (int r = 0; r < RPT; r++) h2[r] = ld2(&hb[(r0 + r) * HSZ + kc]);
                #pragma unroll
                for (int g = 0; g < 4; g++) {
                    ulonglong2 w2 = ld2(&sW[(g * HSZ + u) * HSZ + kc]);
                    #pragma unroll
                    for (int r = 0; r < RPT; r++) {
                        ffma2(acc[r][g], w2.x, h2[r].x);
                        ffma2(acc[r][g], w2.y, h2[r].y);
                    }
                }
            }
            float* hnb = sH + (1 - p) * BR * HSZ;
            #pragma unroll
            for (int r = 0; r < RPT; r++) {
                float zi = psum(acc[r][0]);
                float zf = psum(acc[r][1]);
                float zg = psum(acc[r][2]);
                float zo = psum(acc[r][3]);
                float cn = sigf(zf) * c[r] + sigf(zi) * tanhfast(zg);
                float hn = sigf(zo) * tanhfast(cn);
                if (t < len[r]) { c[r] = cn; hreg[r] = hn; }
                hnb[(r0 + r) * HSZ + u] = hreg[r];
            }
        }
        __syncthreads();
        p ^= 1;
    }

    // epilogue: out = h1_final @ Wfc^T + b
    if (tid < BR) {
        int g = grow0 + tid;
        if (g < BSZ) {
            float s = bfc[0];
            const float* hb = sH + p * BR * HSZ;
            #pragma unroll 10
            for (int k = 0; k < HSZ; k++) s += hb[tid * HSZ + k] * sWfc[k];
            out[g] = s;
        }
    }
}

// ===========================================================================
// Launch
// ===========================================================================
extern "C" void kernel_launch(void* const* d_in, const int* in_sizes, int n_in,
                              void* d_out, int out_size)
{
    const float* x       = (const float*)d_in[0];
    const int*   lengths = (const int*)  d_in[1];
    const float* Wih0    = (const float*)d_in[2];
    const float* Whh0    = (const float*)d_in[3];
    const float* bih0    = (const float*)d_in[4];
    const float* bhh0    = (const float*)d_in[5];
    const float* Wih1    = (const float*)d_in[6];
    const float* Whh1    = (const float*)d_in[7];
    const float* bih1    = (const float*)d_in[8];
    const float* bhh1    = (const float*)d_in[9];
    const float* Wfc     = (const float*)d_in[10];
    const float* bfc     = (const float*)d_in[11];
    float* out = (float*)d_out;

    const int smA = (40000 + 8000 + 400 + 6000 + 960) * 4 + 32 * 4;   // 221,568
    const int smG = (40000 + 400 + 5000) * 4 + 4096 * 4;              // 197,984
    const int smB = (40000 + 6000 + 128) * 4 + 32 * 4;                // 184,640

    cudaFuncSetAttribute(k_layer0,  cudaFuncAttributeMaxDynamicSharedMemorySize, smA);
    cudaFuncSetAttribute(k_ingemm1, cudaFuncAttributeMaxDynamicSharedMemorySize, smG);
    cudaFuncSetAttribute(k_layer1,  cudaFuncAttributeMaxDynamicSharedMemorySize, smB);

    const int gridR = (BSZ + BR - 1) / BR;   // 137
    k_layer0 <<<gridR, NTHREADS, smA>>>(x, lengths, Wih0, Whh0, bih0, bhh0);
    k_ingemm1<<<148,   NTHREADS, smG>>>(Wih1, lengths, bih1, bhh1);
    k_layer1 <<<gridR, NTHREADS, smB>>>(lengths, Whh1, Wfc, bfc, out);
}

// round 5
// speedup vs baseline: 1.5766x; 1.1746x over previous
#include <cuda_runtime.h>
#include <cuda_bf16.h>
#include <cstdint>
#include <cstddef>

// Problem constants
#define BSZ 4096
#define TSZ 100
#define FSZ 13
#define HSZ 100
#define G4  400
#define KPX 16
#define WPX 20
#define BR  30
#define RPT 6
#define NTHREADS 512

// GEMM constants
#define KP   112      // padded K (100 -> 112, 7 ksteps of 16)
#define LDA  120      // smem row stride (elements), conflict-free
#define LDB  120

// ---------------------------------------------------------------------------
// Scratch (device globals)
// ---------------------------------------------------------------------------
__device__ __nv_bfloat16 g_h0hi[(size_t)BSZ * TSZ * HSZ];  // packed h0, bf16 hi
__device__ __nv_bfloat16 g_h0lo[(size_t)BSZ * TSZ * HSZ];  // packed h0, bf16 lo
__device__ __nv_bfloat16 g_bhi[G4 * KP];                   // W_ih1 split hi (k-padded 0)
__device__ __nv_bfloat16 g_blo[G4 * KP];                   // W_ih1 split lo
__device__ float g_zpack[(size_t)BSZ * TSZ * G4];          // packed z rows
__device__ int   g_off_arr[BSZ + 1];

// ---------------------------------------------------------------------------
// Scalar helpers
// ---------------------------------------------------------------------------
__device__ __forceinline__ float sigf(float x) {
    return __fdividef(1.f, 1.f + __expf(-x));
}
__device__ __forceinline__ float tanhfast(float x) {
    float t = fminf(fmaxf(2.f * x, -30.f), 30.f);
    float e = __expf(t);
    return __fdividef(e - 1.f, e + 1.f);
}
__device__ __forceinline__ void ffma2(unsigned long long &d,
                                      unsigned long long a,
                                      unsigned long long b) {
    asm("fma.rn.f32x2 %0, %1, %2, %0;" : "+l"(d) : "l"(a), "l"(b));
}
__device__ __forceinline__ unsigned long long pk(float lo, float hi) {
    unsigned long long r;
    asm("mov.b64 %0, {%1, %2};" : "=l"(r) : "f"(lo), "f"(hi));
    return r;
}
__device__ __forceinline__ float psum(unsigned long long a) {
    float lo = __uint_as_float((unsigned)(a & 0xffffffffull));
    float hi = __uint_as_float((unsigned)(a >> 32));
    return lo + hi;
}
__device__ __forceinline__ ulonglong2 ld2(const float* p) {
    return *reinterpret_cast<const ulonglong2*>(p);
}
// mma.sync m16n8k16 bf16 (base-arch instruction; no 'a' feature needed)
__device__ __forceinline__ void mma_bf16(float* d, const uint32_t* a,
                                         uint32_t b0, uint32_t b1) {
    asm volatile(
        "mma.sync.aligned.m16n8k16.row.col.f32.bf16.bf16.f32 "
        "{%0,%1,%2,%3}, {%4,%5,%6,%7}, {%8,%9}, {%0,%1,%2,%3};"
        : "+f"(d[0]), "+f"(d[1]), "+f"(d[2]), "+f"(d[3])
        : "r"(a[0]), "r"(a[1]), "r"(a[2]), "r"(a[3]), "r"(b0), "r"(b1));
}

// ===========================================================================
// Kernel S: exclusive prefix scan of lengths (1 CTA)
// ===========================================================================
__global__ void __launch_bounds__(512, 1) k_scan(const int* __restrict__ lengths)
{
    __shared__ int s[512];
    const int tid = threadIdx.x;
    const int base = tid * 8;
    int v[8]; int loc = 0;
    #pragma unroll
    for (int i = 0; i < 8; i++) { v[i] = lengths[base + i]; loc += v[i]; }
    s[tid] = loc;
    __syncthreads();
    for (int d = 1; d < 512; d <<= 1) {
        int t = (tid >= d) ? s[tid - d] : 0;
        __syncthreads();
        s[tid] += t;
        __syncthreads();
    }
    int run = s[tid] - loc;
    #pragma unroll
    for (int i = 0; i < 8; i++) { g_off_arr[base + i] = run; run += v[i]; }
    if (tid == 511) g_off_arr[BSZ] = s[511];
}

// ===========================================================================
// Kernel W: split W_ih1 into bf16 hi/lo with zeroed k-pad
// ===========================================================================
__global__ void __launch_bounds__(256, 1) k_wsplit(const float* __restrict__ Wih1)
{
    int idx = blockIdx.x * 256 + threadIdx.x;
    if (idx < G4 * KP) {
        int n = idx / KP, k = idx % KP;
        float v = (k < HSZ) ? Wih1[n * HSZ + k] : 0.f;
        __nv_bfloat16 hi = __float2bfloat16(v);
        g_bhi[idx] = hi;
        g_blo[idx] = __float2bfloat16(v - __bfloat162float(hi));
    }
}

// ===========================================================================
// Kernel A: layer-0 recurrence, writes packed h0 as bf16 hi/lo
// ===========================================================================
__global__ void __launch_bounds__(NTHREADS, 1)
k_layer0(const float* __restrict__ x, const int* __restrict__ lengths,
         const float* __restrict__ Wih0, const float* __restrict__ Whh0,
         const float* __restrict__ bih0, const float* __restrict__ bhh0)
{
    extern __shared__ float sm[];
    float* sWhh = sm;                    // 40000
    float* sWih = sWhh + 40000;          // 8000
    float* sB   = sWih + 8000;           // 400
    float* sH   = sB   + 400;            // 2 x 3000
    float* sX   = sH   + 6000;           // 2 x 480
    int*   sLen = (int*)(sX + 960);      // 32
    int*   sOff = sLen + 32;             // 32

    const int tid = threadIdx.x;
    const int grow0 = blockIdx.x * BR;

    for (int i = tid; i < 40000; i += NTHREADS) sWhh[i] = Whh0[i];
    for (int i = tid; i < 8000;  i += NTHREADS) {
        int j = i / WPX, kk = i % WPX;
        sWih[i] = (kk < FSZ) ? Wih0[j * FSZ + kk] : 0.f;
    }
    for (int i = tid; i < G4; i += NTHREADS) sB[i] = bih0[i] + bhh0[i];
    for (int i = tid; i < 2 * BR * HSZ; i += NTHREADS) sH[i] = 0.f;
    if (tid < 32) {
        int g = grow0 + tid;
        bool ok = (tid < BR && g < BSZ);
        sLen[tid] = ok ? lengths[g] : 0;
        sOff[tid] = ok ? g_off_arr[g] : 0;
    }
    if (tid < BR * KPX) {
        int r = tid >> 4, kk = tid & 15;
        int g = grow0 + r;
        sX[tid] = (kk < FSZ && g < BSZ) ? x[(size_t)g * (TSZ * FSZ) + kk] : 0.f;
    }
    __syncthreads();

    const int u  = tid % HSZ;
    const int yg = tid / HSZ;
    const bool act = (tid < 500);
    const int r0 = yg * RPT;

    int Lmax = 0;
    #pragma unroll
    for (int r = 0; r < BR; r++) Lmax = max(Lmax, sLen[r]);

    float c[RPT], hreg[RPT]; int len[RPT]; int offr[RPT];
    #pragma unroll
    for (int r = 0; r < RPT; r++) {
        c[r] = 0.f; hreg[r] = 0.f;
        len[r]  = act ? sLen[r0 + r] : 0;
        offr[r] = act ? sOff[r0 + r] : 0;
    }
    float bi = 0.f, bf = 0.f, bg_ = 0.f, bo = 0.f;
    if (act) { bi = sB[u]; bf = sB[u + 100]; bg_ = sB[u + 200]; bo = sB[u + 300]; }

    int p = 0;
    #pragma unroll 1
    for (int t = 0; t < Lmax; t++) {
        float xs = 0.f;
        const bool st = (tid < BR * KPX) && (t + 1 < Lmax);
        if (st) {
            int r = tid >> 4, kk = tid & 15;
            int g = grow0 + r;
            xs = (kk < FSZ && g < BSZ)
               ? x[(size_t)g * (TSZ * FSZ) + (t + 1) * FSZ + kk] : 0.f;
        }

        unsigned long long acc[RPT][4];
        if (act) {
            #pragma unroll
            for (int r = 0; r < RPT; r++) {
                acc[r][0] = pk(bi, 0.f); acc[r][1] = pk(bf, 0.f);
                acc[r][2] = pk(bg_, 0.f); acc[r][3] = pk(bo, 0.f);
            }
            const float* hb = sH + p * BR * HSZ;
            const float* xb = sX + p * BR * KPX;
            #pragma unroll
            for (int kc = 0; kc < KPX; kc += 4) {
                ulonglong2 h2[RPT];
                #pragma unroll
                for (int r = 0; r < RPT; r++) h2[r] = ld2(&xb[(r0 + r) * KPX + kc]);
                #pragma unroll
                for (int g = 0; g < 4; g++) {
                    ulonglong2 w2 = ld2(&sWih[(g * HSZ + u) * WPX + kc]);
                    #pragma unroll
                    for (int r = 0; r < RPT; r++) {
                        ffma2(acc[r][g], w2.x, h2[r].x);
                        ffma2(acc[r][g], w2.y, h2[r].y);
                    }
                }
            }
            #pragma unroll 5
            for (int kc = 0; kc < HSZ; kc += 4) {
                ulonglong2 h2[RPT];
                #pragma unroll
                for (int r = 0; r < RPT; r++) h2[r] = ld2(&hb[(r0 + r) * HSZ + kc]);
                #pragma unroll
                for (int g = 0; g < 4; g++) {
                    ulonglong2 w2 = ld2(&sWhh[(g * HSZ + u) * HSZ + kc]);
                    #pragma unroll
                    for (int r = 0; r < RPT; r++) {
                        ffma2(acc[r][g], w2.x, h2[r].x);
                        ffma2(acc[r][g], w2.y, h2[r].y);
                    }
                }
            }
        }
        if (st) sX[(1 - p) * BR * KPX + tid] = xs;

        if (act) {
            float* hnb = sH + (1 - p) * BR * HSZ;
            #pragma unroll
            for (int r = 0; r < RPT; r++) {
                float zi = psum(acc[r][0]);
                float zf = psum(acc[r][1]);
                float zg = psum(acc[r][2]);
                float zo = psum(acc[r][3]);
                float cn = sigf(zf) * c[r] + sigf(zi) * tanhfast(zg);
                float hn = sigf(zo) * tanhfast(cn);
                if (t < len[r]) {
                    c[r] = cn; hreg[r] = hn;
                    size_t o = ((size_t)offr[r] + t) * HSZ + u;
                    __nv_bfloat16 hi = __float2bfloat16(hn);
                    g_h0hi[o] = hi;
                    g_h0lo[o] = __float2bfloat16(hn - __bfloat162float(hi));
                }
                hnb[(r0 + r) * HSZ + u] = hreg[r];
            }
        }
        __syncthreads();
        p ^= 1;
    }
}

// ===========================================================================
// Kernel G (mma.sync bf16x3): zpack = h0pack @ Wih1^T + bias1
//   CTA tile M=128 x N=200 (half of 4H); 16 warps = 4M x 4N
// ===========================================================================
__global__ void __launch_bounds__(512, 1)
k_gemm_mma(const float* __restrict__ bih1, const float* __restrict__ bhh1)
{
    extern __shared__ char smc[];
    float*          sBias = (float*)smc;                          // 1600 B
    __nv_bfloat16*  sAhi  = (__nv_bfloat16*)(smc + 1600);         // 30720
    __nv_bfloat16*  sAlo  = (__nv_bfloat16*)(smc + 32320);        // 30720
    __nv_bfloat16*  sBhi  = (__nv_bfloat16*)(smc + 63040);        // 53760
    __nv_bfloat16*  sBlo  = (__nv_bfloat16*)(smc + 116800);       // 53760

    const int tid  = threadIdx.x;
    const int wid  = tid >> 5, lane = tid & 31;
    const int g    = lane >> 2, tg = lane & 3;
    const int wm   = (wid & 3) * 32;     // warp m offset (0,32,64,96)
    const int wn   = (wid >> 2) * 56;    // warp n offset in half (0,56,112,168)

    // init: bias, zero A k-pad (cols 100..119), zero B pad rows (200..223)
    for (int i = tid; i < G4; i += 512) sBias[i] = bih1[i] + bhh1[i];
    for (int i = tid; i < 128 * 20; i += 512) {
        int r = i / 20, kk = 100 + i % 20;
        sAhi[r * LDA + kk] = __float2bfloat16(0.f);
        sAlo[r * LDA + kk] = __float2bfloat16(0.f);
    }
    for (int i = tid; i < 24 * LDB; i += 512) {
        int r = 200 + i / LDB, kk = i % LDB;
        sBhi[r * LDB + kk] = __float2bfloat16(0.f);
        sBlo[r * LDB + kk] = __float2bfloat16(0.f);
    }

    const int Mpack  = g_off_arr[BSZ];
    const int ntiles = (Mpack + 127) >> 7;
    const int nitems = ntiles * 2;
    int curHalf = -1;

    #pragma unroll 1
    for (int it = blockIdx.x; it < nitems; it += gridDim.x) {
        const int half  = (it >= ntiles) ? 1 : 0;
        const int mtile = it - half * ntiles;
        const size_t m0 = (size_t)mtile << 7;
        const int jo    = half * 200;

        __syncthreads();   // previous item's fragment reads done
        if (half != curHalf) {
            curHalf = half;
            // B half: 200 rows x 112 k, uint4 = 8 bf16
            #pragma unroll 1
            for (int i = tid; i < 200 * 14; i += 512) {
                int n = i / 14, kc = (i % 14) * 8;
                size_t go = (size_t)(jo + n) * KP + kc;
                *(uint4*)&sBhi[n * LDB + kc] = *(const uint4*)&g_bhi[go];
                *(uint4*)&sBlo[n * LDB + kc] = *(const uint4*)&g_blo[go];
            }
        }
        // A tile: 128 rows x 100 k, uint2 = 4 bf16
        #pragma unroll 1
        for (int i = tid; i < 128 * 25; i += 512) {
            int r = i / 25, kc = (i % 25) * 4;
            size_t go = (m0 + r) * HSZ + kc;
            *(uint2*)&sAhi[r * LDA + kc] = *(const uint2*)&g_h0hi[go];
            *(uint2*)&sAlo[r * LDA + kc] = *(const uint2*)&g_h0lo[go];
        }
        __syncthreads();

        float D[2][7][4];
        #pragma unroll
        for (int mt = 0; mt < 2; mt++)
            #pragma unroll
            for (int nt = 0; nt < 7; nt++)
                #pragma unroll
                for (int q = 0; q < 4; q++) D[mt][nt][q] = 0.f;

        #pragma unroll 1
        for (int term = 0; term < 3; term++) {
            const __nv_bfloat16* A = (term == 2) ? sAlo : sAhi;
            const __nv_bfloat16* B = (term == 1) ? sBlo : sBhi;
            #pragma unroll
            for (int ks = 0; ks < 7; ks++) {
                const int kb = ks * 16;
                uint32_t a[2][4];
                #pragma unroll
                for (int mt = 0; mt < 2; mt++) {
                    const __nv_bfloat16* ar = A + (wm + mt * 16 + g) * LDA + kb + 2 * tg;
                    a[mt][0] = *(const uint32_t*)ar;
                    a[mt][1] = *(const uint32_t*)(ar + 8 * LDA);
                    a[mt][2] = *(const uint32_t*)(ar + 8);
                    a[mt][3] = *(const uint32_t*)(ar + 8 * LDA + 8);
                }
                #pragma unroll
                for (int nt = 0; nt < 7; nt++) {
                    const __nv_bfloat16* br = B + (wn + nt * 8 + g) * LDB + kb + 2 * tg;
                    uint32_t b0 = *(const uint32_t*)br;
                    uint32_t b1 = *(const uint32_t*)(br + 8);
                    mma_bf16(D[0][nt], a[0], b0, b1);
                    mma_bf16(D[1][nt], a[1], b0, b1);
                }
            }
        }

        // epilogue: +bias, guarded float2 stores
        #pragma unroll
        for (int mt = 0; mt < 2; mt++) {
            #pragma unroll
            for (int nt = 0; nt < 7; nt++) {
                int n_rel = wn + nt * 8 + 2 * tg;
                if (n_rel < 200) {
                    int ncol = jo + n_rel;
                    float b0v = sBias[ncol], b1v = sBias[ncol + 1];
                    size_t R = m0 + wm + mt * 16 + g;
                    if (R < (size_t)Mpack) {
                        float2 v = make_float2(D[mt][nt][0] + b0v, D[mt][nt][1] + b1v);
                        *(float2*)&g_zpack[R * G4 + ncol] = v;
                    }
                    if (R + 8 < (size_t)Mpack) {
                        float2 v = make_float2(D[mt][nt][2] + b0v, D[mt][nt][3] + b1v);
                        *(float2*)&g_zpack[(R + 8) * G4 + ncol] = v;
                    }
                }
            }
        }
    }
}

// ===========================================================================
// Kernel B: layer-1 recurrence reading packed z + fc epilogue
// ===========================================================================
__global__ void __launch_bounds__(NTHREADS, 1)
k_layer1(const int* __restrict__ lengths, const float* __restrict__ Whh1,
         const float* __restrict__ Wfc, const float* __restrict__ bfc,
         float* __restrict__ out)
{
    extern __shared__ float sm[];
    float* sW   = sm;                    // 40000
    float* sH   = sW + 40000;            // 2 x 3000
    float* sWfc = sH + 6000;             // 128
    int*   sLen = (int*)(sWfc + 128);    // 32
    int*   sOff = sLen + 32;             // 32

    const int tid = threadIdx.x;
    const int grow0 = blockIdx.x * BR;
    for (int i = tid; i < 40000; i += NTHREADS) sW[i] = Whh1[i];
    for (int i = tid; i < 2 * BR * HSZ; i += NTHREADS) sH[i] = 0.f;
    if (tid < 128) sWfc[tid] = (tid < HSZ) ? Wfc[tid] : 0.f;
    if (tid < 32) {
        int g = grow0 + tid;
        bool ok = (tid < BR && g < BSZ);
        sLen[tid] = ok ? lengths[g] : 0;
        sOff[tid] = ok ? g_off_arr[g] : 0;
    }
    __syncthreads();

    const int u  = tid % HSZ;
    const int yg = tid / HSZ;
    const bool act = (tid < 500);
    const int r0 = yg * RPT;

    int Lmax = 0;
    #pragma unroll
    for (int r = 0; r < BR; r++) Lmax = max(Lmax, sLen[r]);

    float c[RPT], hreg[RPT]; int len[RPT]; int zoff[RPT]; bool rv[RPT];
    #pragma unroll
    for (int r = 0; r < RPT; r++) {
        c[r] = 0.f; hreg[r] = 0.f;
        len[r]  = act ? sLen[r0 + r] : 0;
        zoff[r] = act ? sOff[r0 + r] : 0;
        rv[r]   = act && (grow0 + r0 + r < BSZ);
    }

    // prologue: prefetch z(0)
    float zn[RPT][4];
    #pragma unroll
    for (int r = 0; r < RPT; r++) {
        size_t zb = (size_t)zoff[r] * G4;
        #pragma unroll
        for (int g = 0; g < 4; g++)
            zn[r][g] = rv[r] ? g_zpack[zb + g * HSZ + u] : 0.f;
    }

    int p = 0;
    #pragma unroll 1
    for (int t = 0; t < Lmax; t++) {
        unsigned long long acc[RPT][4];
        if (act) {
            #pragma unroll
            for (int r = 0; r < RPT; r++)
                #pragma unroll
                for (int g = 0; g < 4; g++) acc[r][g] = pk(zn[r][g], 0.f);
        }
        // prefetch z(t+1) for rows still running
        #pragma unroll
        for (int r = 0; r < RPT; r++) {
            bool ld = rv[r] && (t + 1 < len[r]);
            size_t zb = ((size_t)zoff[r] + t + 1) * G4;
            #pragma unroll
            for (int g = 0; g < 4; g++)
                zn[r][g] = ld ? g_zpack[zb + g * HSZ + u] : 0.f;
        }
        if (act) {
            const float* hb = sH + p * BR * HSZ;
            #pragma unroll 5
            for (int kc = 0; kc < HSZ; kc += 4) {
                ulonglong2 h2[RPT];
                #pragma unroll
                for (int r = 0; r < RPT; r++) h2[r] = ld2(&hb[(r0 + r) * HSZ + kc]);
                #pragma unroll
                for (int g = 0; g < 4; g++) {
                    ulonglong2 w2 = ld2(&sW[(g * HSZ + u) * HSZ + kc]);
                    #pragma unroll
                    for (int r = 0; r < RPT; r++) {
                        ffma2(acc[r][g], w2.x, h2[r].x);
                        ffma2(acc[r][g], w2.y, h2[r].y);
                    }
                }
            }
            float* hnb = sH + (1 - p) * BR * HSZ;
            #pragma unroll
            for (int r = 0; r < RPT; r++) {
                float zi = psum(acc[r][0]);
                float zf = psum(acc[r][1]);
                float zg = psum(acc[r][2]);
                float zo = psum(acc[r][3]);
                float cn = sigf(zf) * c[r] + sigf(zi) * tanhfast(zg);
                float hn = sigf(zo) * tanhfast(cn);
                if (t < len[r]) { c[r] = cn; hreg[r] = hn; }
                hnb[(r0 + r) * HSZ + u] = hreg[r];
            }
        }
        __syncthreads();
        p ^= 1;
    }

    if (tid < BR) {
        int g = grow0 + tid;
        if (g < BSZ) {
            float s = bfc[0];
            const float* hb = sH + p * BR * HSZ;
            #pragma unroll 10
            for (int k = 0; k < HSZ; k++) s += hb[tid * HSZ + k] * sWfc[k];
            out[g] = s;
        }
    }
}

// ===========================================================================
// Launch
// ===========================================================================
extern "C" void kernel_launch(void* const* d_in, const int* in_sizes, int n_in,
                              void* d_out, int out_size)
{
    const float* x       = (const float*)d_in[0];
    const int*   lengths = (const int*)  d_in[1];
    const float* Wih0    = (const float*)d_in[2];
    const float* Whh0    = (const float*)d_in[3];
    const float* bih0    = (const float*)d_in[4];
    const float* bhh0    = (const float*)d_in[5];
    const float* Wih1    = (const float*)d_in[6];
    const float* Whh1    = (const float*)d_in[7];
    const float* bih1    = (const float*)d_in[8];
    const float* bhh1    = (const float*)d_in[9];
    const float* Wfc     = (const float*)d_in[10];
    const float* bfc     = (const float*)d_in[11];
    float* out = (float*)d_out;

    const int smA = (40000 + 8000 + 400 + 6000 + 960) * 4 + 64 * 4;   // 221,696
    const int smG = 1600 + 2 * 30720 + 2 * 53760;                      // 170,560
    const int smB = (40000 + 6000 + 128) * 4 + 64 * 4;                 // 184,768

    cudaFuncSetAttribute(k_layer0,   cudaFuncAttributeMaxDynamicSharedMemorySize, smA);
    cudaFuncSetAttribute(k_gemm_mma, cudaFuncAttributeMaxDynamicSharedMemorySize, smG);
    cudaFuncSetAttribute(k_layer1,   cudaFuncAttributeMaxDynamicSharedMemorySize, smB);

    const int gridR = (BSZ + BR - 1) / BR;   // 137
    k_scan    <<<1,    512>>>(lengths);
    k_wsplit  <<<(G4 * KP + 255) / 256, 256>>>(Wih1);
    k_layer0  <<<gridR, NTHREADS, smA>>>(x, lengths, Wih0, Whh0, bih0, bhh0);
    k_gemm_mma<<<148,   512,      smG>>>(bih1, bhh1);
    k_layer1  <<<gridR, NTHREADS, smB>>>(lengths, Whh1, Wfc, bfc, out);
}

// round 6
// speedup vs baseline: 2.1595x; 1.3697x over previous
#include <cuda_runtime.h>
#include <cuda_bf16.h>
#include <cstdint>
#include <cstddef>

// Problem constants
#define BSZ 4096
#define TSZ 100
#define FSZ 13
#define HSZ 100
#define G4  400

// GEMM (k_gemm_mma) constants
#define KP   112
#define LDA  120
#define LDB  120

// Recurrent tensor kernel constants
#define RW    13            // warps
#define RTH   (RW*32)       // 416 threads
#define W2N   23296         // W2 words per split: 52 ntiles * 7 kt * 8 pairs * 8 g
#define HROW  57            // hbuf row stride (bf16x2 words)
#define HBUFW (32*HROW)     // 1824 words per buffer

// ---------------------------------------------------------------------------
// Scratch (device globals)
// ---------------------------------------------------------------------------
__device__ __nv_bfloat16 g_h0hi[(size_t)BSZ * TSZ * HSZ];
__device__ __nv_bfloat16 g_h0lo[(size_t)BSZ * TSZ * HSZ];
__device__ __nv_bfloat16 g_bhi[G4 * KP];      // W_ih1 split (gemm layout)
__device__ __nv_bfloat16 g_blo[G4 * KP];
__device__ float g_zpack [(size_t)BSZ * TSZ * G4];  // layer-1 z (from gemm)
__device__ float g_z0pack[(size_t)BSZ * TSZ * G4];  // layer-0 z (bias0 + Wx)
__device__ int   g_off_arr[BSZ + 1];
// recurrent W (fragment-native tile layout), hi/lo splits, both layers
__device__ uint32_t g_w2hi0[W2N], g_w2lo0[W2N];
__device__ uint32_t g_w2hi1[W2N], g_w2lo1[W2N];

// ---------------------------------------------------------------------------
// Scalar helpers
// ---------------------------------------------------------------------------
__device__ __forceinline__ float sigf(float x) {
    return __fdividef(1.f, 1.f + __expf(-x));
}
__device__ __forceinline__ float tanhfast(float x) {
    float t = fminf(fmaxf(2.f * x, -30.f), 30.f);
    float e = __expf(t);
    return __fdividef(e - 1.f, e + 1.f);
}
__device__ __forceinline__ void ffma2(unsigned long long &d,
                                      unsigned long long a,
                                      unsigned long long b) {
    asm("fma.rn.f32x2 %0, %1, %2, %0;" : "+l"(d) : "l"(a), "l"(b));
}
__device__ __forceinline__ unsigned long long pk(float lo, float hi) {
    unsigned long long r;
    asm("mov.b64 %0, {%1, %2};" : "=l"(r) : "f"(lo), "f"(hi));
    return r;
}
__device__ __forceinline__ float psum(unsigned long long a) {
    float lo = __uint_as_float((unsigned)(a & 0xffffffffull));
    float hi = __uint_as_float((unsigned)(a >> 32));
    return lo + hi;
}
// mma.sync m16n8k16 bf16 (base-arch)
__device__ __forceinline__ void mma_bf16(float* d, const uint32_t* a,
                                         uint32_t b0, uint32_t b1) {
    asm volatile(
        "mma.sync.aligned.m16n8k16.row.col.f32.bf16.bf16.f32 "
        "{%0,%1,%2,%3}, {%4,%5,%6,%7}, {%8,%9}, {%0,%1,%2,%3};"
        : "+f"(d[0]), "+f"(d[1]), "+f"(d[2]), "+f"(d[3])
        : "r"(a[0]), "r"(a[1]), "r"(a[2]), "r"(a[3]), "r"(b0), "r"(b1));
}
__device__ __forceinline__ uint32_t pack_bf16x2(float a, float b) {
    __nv_bfloat16 x = __float2bfloat16(a), y = __float2bfloat16(b);
    return (uint32_t)__bfloat16_as_ushort(x)
         | ((uint32_t)__bfloat16_as_ushort(y) << 16);
}

// ===========================================================================
// Kernel S: exclusive prefix scan of lengths (1 CTA)
// ===========================================================================
__global__ void __launch_bounds__(512, 1) k_scan(const int* __restrict__ lengths)
{
    __shared__ int s[512];
    const int tid = threadIdx.x;
    const int base = tid * 8;
    int v[8]; int loc = 0;
    #pragma unroll
    for (int i = 0; i < 8; i++) { v[i] = lengths[base + i]; loc += v[i]; }
    s[tid] = loc;
    __syncthreads();
    for (int d = 1; d < 512; d <<= 1) {
        int t = (tid >= d) ? s[tid - d] : 0;
        __syncthreads();
        s[tid] += t;
        __syncthreads();
    }
    int run = s[tid] - loc;
    #pragma unroll
    for (int i = 0; i < 8; i++) { g_off_arr[base + i] = run; run += v[i]; }
    if (tid == 511) g_off_arr[BSZ] = s[511];
}

// ===========================================================================
// Kernel W1: split W_ih1 into bf16 hi/lo (gemm layout, k-padded)
// ===========================================================================
__global__ void __launch_bounds__(256, 1) k_wsplit(const float* __restrict__ Wih1)
{
    int idx = blockIdx.x * 256 + threadIdx.x;
    if (idx < G4 * KP) {
        int n = idx / KP, k = idx % KP;
        float v = (k < HSZ) ? Wih1[n * HSZ + k] : 0.f;
        __nv_bfloat16 hi = __float2bfloat16(v);
        g_bhi[idx] = hi;
        g_blo[idx] = __float2bfloat16(v - __bfloat162float(hi));
    }
}

// ===========================================================================
// Kernel W2: prepare Whh in recurrent fragment-native layout
//   word idx = ((n*7 + kt)*8 + p)*8 + g ; value = {W[row][k], W[row][k+1]}
//   row416 = n*8+g -> gate = row416/104, u = row416%104 ; k = kt*16 + 2p
// ===========================================================================
__global__ void __launch_bounds__(256, 1)
k_wprep(const float* __restrict__ W, uint32_t* __restrict__ dhi,
        uint32_t* __restrict__ dlo)
{
    int idx = blockIdx.x * 256 + threadIdx.x;
    if (idx >= W2N) return;
    int gg   = idx & 7;
    int p    = (idx >> 3) & 7;
    int rest = idx >> 6;
    int kt   = rest % 7;
    int n    = rest / 7;
    int row  = n * 8 + gg;
    int gate = row / 104, u = row % 104;
    int k    = kt * 16 + 2 * p;
    float f0 = (u < HSZ && k     < HSZ) ? W[(gate * HSZ + u) * HSZ + k]     : 0.f;
    float f1 = (u < HSZ && k + 1 < HSZ) ? W[(gate * HSZ + u) * HSZ + k + 1] : 0.f;
    __nv_bfloat16 h0 = __float2bfloat16(f0), h1 = __float2bfloat16(f1);
    float r0 = f0 - __bfloat162float(h0), r1 = f1 - __bfloat162float(h1);
    dhi[idx] = (uint32_t)__bfloat16_as_ushort(h0)
             | ((uint32_t)__bfloat16_as_ushort(h1) << 16);
    dlo[idx] = (uint32_t)__bfloat16_as_ushort(__float2bfloat16(r0))
             | ((uint32_t)__bfloat16_as_ushort(__float2bfloat16(r1)) << 16);
}

// ===========================================================================
// Kernel Z0: g_z0pack = bias0 + x @ Wih0^T  (packed rows, fp32 FFMA2)
// ===========================================================================
__global__ void __launch_bounds__(512, 1)
k_zx0(const float* __restrict__ x, const int* __restrict__ lengths,
      const float* __restrict__ Wih0,
      const float* __restrict__ bih0, const float* __restrict__ bhh0)
{
    __shared__ float sX[1400];
    __shared__ int sLen[32], sOff[32];
    const int tid = threadIdx.x;
    const int grow0 = blockIdx.x * 32;
    if (tid < 32) {
        sLen[tid] = lengths[grow0 + tid];
        sOff[tid] = g_off_arr[grow0 + tid];
    }
    const int u = tid;
    const bool act = (u < G4);
    unsigned long long wp[7];
    float b = 0.f;
    if (act) {
        float wr[14];
        #pragma unroll
        for (int k = 0; k < FSZ; k++) wr[k] = Wih0[u * FSZ + k];
        wr[13] = 0.f;
        #pragma unroll
        for (int i = 0; i < 7; i++) wp[i] = pk(wr[2*i], wr[2*i+1]);
        b = bih0[u] + bhh0[u];
    }
    __syncthreads();

    for (int r = 0; r < 32; r++) {
        const int len = sLen[r], off = sOff[r];
        __syncthreads();
        const float* xs = x + (size_t)(grow0 + r) * (TSZ * FSZ);
        for (int i = tid; i < 1400; i += 512) {
            int t = i / 14, k = i % 14;
            sX[i] = (k < FSZ) ? xs[t * FSZ + k] : 0.f;
        }
        __syncthreads();
        if (act) {
            for (int t = 0; t < len; t++) {
                unsigned long long acc = pk(b, 0.f);
                #pragma unroll
                for (int kp = 0; kp < 7; kp++)
                    ffma2(acc, wp[kp], *(const unsigned long long*)&sX[t*14 + 2*kp]);
                g_z0pack[(size_t)(off + t) * G4 + u] = psum(acc);
            }
        }
    }
}

// ===========================================================================
// Kernel R: tensor-core recurrent LSTM layer (MODE 0: layer0, 1: layer1+fc)
//   grid 128 x 416 threads (13 warps); 32 batch rows per CTA (M=32)
//   N padded 416 (gate stride 104); K padded 112; bf16x3 split MMA
// ===========================================================================
template<int MODE>
__global__ void __launch_bounds__(RTH, 1)
k_rec(const int* __restrict__ lengths,
      const float* __restrict__ Wfc, const float* __restrict__ bfc,
      float* __restrict__ out)
{
    extern __shared__ char smc[];
    uint32_t* sWhi = (uint32_t*)(smc);                 // 93184 B
    uint32_t* sWlo = (uint32_t*)(smc + 93184);         // 93184 B
    uint32_t* sHhi = (uint32_t*)(smc + 186368);        // 2*1824 words
    uint32_t* sHlo = (uint32_t*)(smc + 200960);        // 2*1824 words
    int*   sLen = (int*)(smc + 215552);
    int*   sOff = (int*)(smc + 215680);
    float* sWf  = (float*)(smc + 215808);              // 100 floats
    float* sHF  = (float*)(smc + 186368);              // fc reuse (3200 floats)

    const uint32_t* gwhi = MODE ? g_w2hi1 : g_w2hi0;
    const uint32_t* gwlo = MODE ? g_w2lo1 : g_w2lo0;
    const float*    zsrc = MODE ? g_zpack : g_z0pack;

    const int tid = threadIdx.x;
    const int grow0 = blockIdx.x * 32;

    for (int i = tid; i < W2N; i += RTH) { sWhi[i] = gwhi[i]; sWlo[i] = gwlo[i]; }
    for (int i = tid; i < 2 * HBUFW; i += RTH) { sHhi[i] = 0u; sHlo[i] = 0u; }
    if (tid < 32) {
        sLen[tid] = lengths[grow0 + tid];
        sOff[tid] = g_off_arr[grow0 + tid];
    }
    if (MODE == 1 && tid < HSZ) sWf[tid] = Wfc[tid];
    __syncthreads();

    int Lmax = 0;
    #pragma unroll
    for (int r = 0; r < 32; r++) Lmax = max(Lmax, sLen[r]);

    const int w = tid >> 5, lane = tid & 31;
    const int g = lane >> 2, tg = lane & 3;
    const int u0 = w * 8 + 2 * tg;          // cols u0, u0+1 (per gate)
    const bool cv = (u0 < HSZ);             // u0<=98 -> u0+1<=99 also valid

    int rown[4], lenr[4], offr[4];
    #pragma unroll
    for (int ri = 0; ri < 4; ri++) {
        int mt = ri >> 1, rh = ri & 1;
        rown[ri] = mt * 16 + rh * 8 + g;
        lenr[ri] = sLen[rown[ri]];
        offr[ri] = sOff[rown[ri]];
    }
    float c[4][2] = {{0.f,0.f},{0.f,0.f},{0.f,0.f},{0.f,0.f}};
    float h[4][2] = {{0.f,0.f},{0.f,0.f},{0.f,0.f},{0.f,0.f}};

    int p = 0;
    #pragma unroll 1
    for (int t = 0; t < Lmax; t++) {
        // z(t) prefetch (consumed after the long MMA block)
        float zn[4][4][2];
        #pragma unroll
        for (int ri = 0; ri < 4; ri++) {
            const bool lv = cv && (t < lenr[ri]);
            const size_t zb = (size_t)(offr[ri] + t) * G4;
            #pragma unroll
            for (int G = 0; G < 4; G++) {
                zn[ri][G][0] = lv ? zsrc[zb + G * HSZ + u0]     : 0.f;
                zn[ri][G][1] = lv ? zsrc[zb + G * HSZ + u0 + 1] : 0.f;
            }
        }

        float D[2][4][4];
        #pragma unroll
        for (int mt = 0; mt < 2; mt++)
            #pragma unroll
            for (int G = 0; G < 4; G++)
                #pragma unroll
                for (int q = 0; q < 4; q++) D[mt][G][q] = 0.f;

        const uint32_t* Hh = sHhi + p * HBUFW;
        const uint32_t* Hl = sHlo + p * HBUFW;
        #pragma unroll
        for (int kt = 0; kt < 7; kt++) {
            uint32_t ahi[2][4], alo[2][4];
            const int kb = kt * 8 + tg;
            #pragma unroll
            for (int mt = 0; mt < 2; mt++) {
                const int ra = mt * 16 + g;
                ahi[mt][0] = Hh[ ra      * HROW + kb];
                ahi[mt][1] = Hh[(ra + 8) * HROW + kb];
                ahi[mt][2] = Hh[ ra      * HROW + kb + 4];
                ahi[mt][3] = Hh[(ra + 8) * HROW + kb + 4];
                alo[mt][0] = Hl[ ra      * HROW + kb];
                alo[mt][1] = Hl[(ra + 8) * HROW + kb];
                alo[mt][2] = Hl[ ra      * HROW + kb + 4];
                alo[mt][3] = Hl[(ra + 8) * HROW + kb + 4];
            }
            #pragma unroll
            for (int G = 0; G < 4; G++) {
                const int n = G * 13 + w;
                const int base = (n * 7 + kt) * 64;
                const uint32_t bh0 = sWhi[base + tg * 8 + g];
                const uint32_t bh1 = sWhi[base + (tg + 4) * 8 + g];
                const uint32_t bl0 = sWlo[base + tg * 8 + g];
                const uint32_t bl1 = sWlo[base + (tg + 4) * 8 + g];
                #pragma unroll
                for (int mt = 0; mt < 2; mt++) {
                    mma_bf16(D[mt][G], ahi[mt], bh0, bh1);
                    mma_bf16(D[mt][G], alo[mt], bh0, bh1);
                    mma_bf16(D[mt][G], ahi[mt], bl0, bl1);
                }
            }
        }

        // activation + state update + stage h(t+1)
        uint32_t* Nh = sHhi + (1 - p) * HBUFW;
        uint32_t* Nl = sHlo + (1 - p) * HBUFW;
        #pragma unroll
        for (int ri = 0; ri < 4; ri++) {
            const int mt = ri >> 1, rh = ri & 1;
            const bool upd = cv && (t < lenr[ri]);
            #pragma unroll
            for (int j = 0; j < 2; j++) {
                float zi = D[mt][0][rh * 2 + j] + zn[ri][0][j];
                float zf = D[mt][1][rh * 2 + j] + zn[ri][1][j];
                float zg = D[mt][2][rh * 2 + j] + zn[ri][2][j];
                float zo = D[mt][3][rh * 2 + j] + zn[ri][3][j];
                float cn = sigf(zf) * c[ri][j] + sigf(zi) * tanhfast(zg);
                float hn = sigf(zo) * tanhfast(cn);
                if (upd) { c[ri][j] = cn; h[ri][j] = hn; }
            }
            __nv_bfloat16 b0 = __float2bfloat16(h[ri][0]);
            __nv_bfloat16 b1 = __float2bfloat16(h[ri][1]);
            float l0 = h[ri][0] - __bfloat162float(b0);
            float l1 = h[ri][1] - __bfloat162float(b1);
            uint32_t hw = (uint32_t)__bfloat16_as_ushort(b0)
                        | ((uint32_t)__bfloat16_as_ushort(b1) << 16);
            uint32_t lw = pack_bf16x2(l0, l1);
            const int word = rown[ri] * HROW + w * 4 + tg;
            Nh[word] = hw; Nl[word] = lw;
            if (MODE == 0 && upd) {
                size_t o = ((size_t)offr[ri] + t) * HSZ + u0;
                *(uint32_t*)&g_h0hi[o] = hw;
                *(uint32_t*)&g_h0lo[o] = lw;
            }
        }
        __syncthreads();
        p ^= 1;
    }

    if (MODE == 1) {
        // fc epilogue: out = h1_final @ Wfc^T + b
        #pragma unroll
        for (int ri = 0; ri < 4; ri++) {
            if (cv) {
                sHF[rown[ri] * HSZ + u0]     = h[ri][0];
                sHF[rown[ri] * HSZ + u0 + 1] = h[ri][1];
            }
        }
        __syncthreads();
        if (tid < 32) {
            float s = bfc[0];
            #pragma unroll 10
            for (int k = 0; k < HSZ; k++) s += sHF[tid * HSZ + k] * sWf[k];
            out[grow0 + tid] = s;
        }
    }
}

// ===========================================================================
// Kernel G (mma.sync bf16x3): zpack = h0pack @ Wih1^T + bias1  (unchanged)
// ===========================================================================
__global__ void __launch_bounds__(512, 1)
k_gemm_mma(const float* __restrict__ bih1, const float* __restrict__ bhh1)
{
    extern __shared__ char smc[];
    float*          sBias = (float*)smc;
    __nv_bfloat16*  sAhi  = (__nv_bfloat16*)(smc + 1600);
    __nv_bfloat16*  sAlo  = (__nv_bfloat16*)(smc + 32320);
    __nv_bfloat16*  sBhi  = (__nv_bfloat16*)(smc + 63040);
    __nv_bfloat16*  sBlo  = (__nv_bfloat16*)(smc + 116800);

    const int tid  = threadIdx.x;
    const int wid  = tid >> 5, lane = tid & 31;
    const int g    = lane >> 2, tg = lane & 3;
    const int wm   = (wid & 3) * 32;
    const int wn   = (wid >> 2) * 56;

    for (int i = tid; i < G4; i += 512) sBias[i] = bih1[i] + bhh1[i];
    for (int i = tid; i < 128 * 20; i += 512) {
        int r = i / 20, kk = 100 + i % 20;
        sAhi[r * LDA + kk] = __float2bfloat16(0.f);
        sAlo[r * LDA + kk] = __float2bfloat16(0.f);
    }
    for (int i = tid; i < 24 * LDB; i += 512) {
        int r = 200 + i / LDB, kk = i % LDB;
        sBhi[r * LDB + kk] = __float2bfloat16(0.f);
        sBlo[r * LDB + kk] = __float2bfloat16(0.f);
    }

    const int Mpack  = g_off_arr[BSZ];
    const int ntiles = (Mpack + 127) >> 7;
    const int nitems = ntiles * 2;
    int curHalf = -1;

    #pragma unroll 1
    for (int it = blockIdx.x; it < nitems; it += gridDim.x) {
        const int half  = (it >= ntiles) ? 1 : 0;
        const int mtile = it - half * ntiles;
        const size_t m0 = (size_t)mtile << 7;
        const int jo    = half * 200;

        __syncthreads();
        if (half != curHalf) {
            curHalf = half;
            #pragma unroll 1
            for (int i = tid; i < 200 * 14; i += 512) {
                int n = i / 14, kc = (i % 14) * 8;
                size_t go = (size_t)(jo + n) * KP + kc;
                *(uint4*)&sBhi[n * LDB + kc] = *(const uint4*)&g_bhi[go];
                *(uint4*)&sBlo[n * LDB + kc] = *(const uint4*)&g_blo[go];
            }
        }
        #pragma unroll 1
        for (int i = tid; i < 128 * 25; i += 512) {
            int r = i / 25, kc = (i % 25) * 4;
            size_t go = (m0 + r) * HSZ + kc;
            *(uint2*)&sAhi[r * LDA + kc] = *(const uint2*)&g_h0hi[go];
            *(uint2*)&sAlo[r * LDA + kc] = *(const uint2*)&g_h0lo[go];
        }
        __syncthreads();

        float D[2][7][4];
        #pragma unroll
        for (int mt = 0; mt < 2; mt++)
            #pragma unroll
            for (int nt = 0; nt < 7; nt++)
                #pragma unroll
                for (int q = 0; q < 4; q++) D[mt][nt][q] = 0.f;

        #pragma unroll 1
        for (int term = 0; term < 3; term++) {
            const __nv_bfloat16* A = (term == 2) ? sAlo : sAhi;
            const __nv_bfloat16* B = (term == 1) ? sBlo : sBhi;
            #pragma unroll
            for (int ks = 0; ks < 7; ks++) {
                const int kb = ks * 16;
                uint32_t a[2][4];
                #pragma unroll
                for (int mt = 0; mt < 2; mt++) {
                    const __nv_bfloat16* ar = A + (wm + mt * 16 + g) * LDA + kb + 2 * tg;
                    a[mt][0] = *(const uint32_t*)ar;
                    a[mt][1] = *(const uint32_t*)(ar + 8 * LDA);
                    a[mt][2] = *(const uint32_t*)(ar + 8);
                    a[mt][3] = *(const uint32_t*)(ar + 8 * LDA + 8);
                }
                #pragma unroll
                for (int nt = 0; nt < 7; nt++) {
                    const __nv_bfloat16* br = B + (wn + nt * 8 + g) * LDB + kb + 2 * tg;
                    uint32_t b0 = *(const uint32_t*)br;
                    uint32_t b1 = *(const uint32_t*)(br + 8);
                    mma_bf16(D[0][nt], a[0], b0, b1);
                    mma_bf16(D[1][nt], a[1], b0, b1);
                }
            }
        }

        #pragma unroll
        for (int mt = 0; mt < 2; mt++) {
            #pragma unroll
            for (int nt = 0; nt < 7; nt++) {
                int n_rel = wn + nt * 8 + 2 * tg;
                if (n_rel < 200) {
                    int ncol = jo + n_rel;
                    float b0v = sBias[ncol], b1v = sBias[ncol + 1];
                    size_t R = m0 + wm + mt * 16 + g;
                    if (R < (size_t)Mpack) {
                        float2 v = make_float2(D[mt][nt][0] + b0v, D[mt][nt][1] + b1v);
                        *(float2*)&g_zpack[R * G4 + ncol] = v;
                    }
                    if (R + 8 < (size_t)Mpack) {
                        float2 v = make_float2(D[mt][nt][2] + b0v, D[mt][nt][3] + b1v);
                        *(float2*)&g_zpack[(R + 8) * G4 + ncol] = v;
                    }
                }
            }
        }
    }
}

// ===========================================================================
// Launch
// ===========================================================================
extern "C" void kernel_launch(void* const* d_in, const int* in_sizes, int n_in,
                              void* d_out, int out_size)
{
    const float* x       = (const float*)d_in[0];
    const int*   lengths = (const int*)  d_in[1];
    const float* Wih0    = (const float*)d_in[2];
    const float* Whh0    = (const float*)d_in[3];
    const float* bih0    = (const float*)d_in[4];
    const float* bhh0    = (const float*)d_in[5];
    const float* Wih1    = (const float*)d_in[6];
    const float* Whh1    = (const float*)d_in[7];
    const float* bih1    = (const float*)d_in[8];
    const float* bhh1    = (const float*)d_in[9];
    const float* Wfc     = (const float*)d_in[10];
    const float* bfc     = (const float*)d_in[11];
    float* out = (float*)d_out;

    uint32_t *w2hi0, *w2lo0, *w2hi1, *w2lo1;
    cudaGetSymbolAddress((void**)&w2hi0, g_w2hi0);
    cudaGetSymbolAddress((void**)&w2lo0, g_w2lo0);
    cudaGetSymbolAddress((void**)&w2hi1, g_w2hi1);
    cudaGetSymbolAddress((void**)&w2lo1, g_w2lo1);

    const int smG = 1600 + 2 * 30720 + 2 * 53760;   // 170,560
    const int smR = 216320;                          // k_rec shared

    cudaFuncSetAttribute(k_gemm_mma, cudaFuncAttributeMaxDynamicSharedMemorySize, smG);
    cudaFuncSetAttribute(k_rec<0>,   cudaFuncAttributeMaxDynamicSharedMemorySize, smR);
    cudaFuncSetAttribute(k_rec<1>,   cudaFuncAttributeMaxDynamicSharedMemorySize, smR);

    k_scan  <<<1, 512>>>(lengths);
    k_wsplit<<<(G4 * KP + 255) / 256, 256>>>(Wih1);
    k_wprep <<<(W2N + 255) / 256, 256>>>(Whh0, w2hi0, w2lo0);
    k_wprep <<<(W2N + 255) / 256, 256>>>(Whh1, w2hi1, w2lo1);
    k_zx0   <<<128, 512>>>(x, lengths, Wih0, bih0, bhh0);
    k_rec<0><<<128, RTH, smR>>>(lengths, nullptr, nullptr, nullptr);
    k_gemm_mma<<<148, 512, smG>>>(bih1, bhh1);
    k_rec<1><<<128, RTH, smR>>>(lengths, Wfc, bfc, out);
}

// round 7
// speedup vs baseline: 2.2781x; 1.0549x over previous
#include <cuda_runtime.h>
#include <cuda_bf16.h>
#include <cstdint>
#include <cstddef>

// Problem constants
#define BSZ 4096
#define TSZ 100
#define FSZ 13
#define HSZ 100
#define G4  400

// GEMM (k_gemm_mma) constants
#define KP   112
#define LDA  120      // bf16 elements (60 words; 60 % 32 = 28 -> ldmatrix conflict-free)
#define LDB  120

// Recurrent tensor kernel constants
#define RW    13
#define RTH   (RW*32)
#define W2N   23296         // words per split
#define HROW  68            // h row stride in words (68 % 32 = 4 -> ldmatrix conflict-free)
#define HBUFW (32*HROW)     // 2176 words per buffer

// ---------------------------------------------------------------------------
// Scratch (device globals)
// ---------------------------------------------------------------------------
__device__ __nv_bfloat16 g_h0hi[(size_t)BSZ * TSZ * HSZ];
__device__ __nv_bfloat16 g_h0lo[(size_t)BSZ * TSZ * HSZ];
__device__ __nv_bfloat16 g_bhi[G4 * KP];
__device__ __nv_bfloat16 g_blo[G4 * KP];
__device__ float g_zpack [(size_t)BSZ * TSZ * G4];
__device__ float g_z0pack[(size_t)BSZ * TSZ * G4];
__device__ int   g_off_arr[BSZ + 1];
__device__ uint32_t g_w2hi0[W2N], g_w2lo0[W2N];
__device__ uint32_t g_w2hi1[W2N], g_w2lo1[W2N];

// ---------------------------------------------------------------------------
// Helpers
// ---------------------------------------------------------------------------
__device__ __forceinline__ float sigf(float x) {              // precise sigmoid
    return __fdividef(1.f, 1.f + __expf(-x));
}
__device__ __forceinline__ float tanha(float x) {             // MUFU.TANH
    float y;
    asm("tanh.approx.f32 %0, %1;" : "=f"(y) : "f"(x));
    return y;
}
__device__ __forceinline__ float siga(float x) {              // approx sigmoid
    return fmaf(0.5f, tanha(0.5f * x), 0.5f);
}
__device__ __forceinline__ void ffma2(unsigned long long &d,
                                      unsigned long long a,
                                      unsigned long long b) {
    asm("fma.rn.f32x2 %0, %1, %2, %0;" : "+l"(d) : "l"(a), "l"(b));
}
__device__ __forceinline__ unsigned long long pk(float lo, float hi) {
    unsigned long long r;
    asm("mov.b64 %0, {%1, %2};" : "=l"(r) : "f"(lo), "f"(hi));
    return r;
}
__device__ __forceinline__ float psum(unsigned long long a) {
    float lo = __uint_as_float((unsigned)(a & 0xffffffffull));
    float hi = __uint_as_float((unsigned)(a >> 32));
    return lo + hi;
}
__device__ __forceinline__ void mma_bf16(float* d, const uint32_t* a,
                                         uint32_t b0, uint32_t b1) {
    asm volatile(
        "mma.sync.aligned.m16n8k16.row.col.f32.bf16.bf16.f32 "
        "{%0,%1,%2,%3}, {%4,%5,%6,%7}, {%8,%9}, {%0,%1,%2,%3};"
        : "+f"(d[0]), "+f"(d[1]), "+f"(d[2]), "+f"(d[3])
        : "r"(a[0]), "r"(a[1]), "r"(a[2]), "r"(a[3]), "r"(b0), "r"(b1));
}
__device__ __forceinline__ void ldsm4(uint32_t* r, uint32_t addr) {
    asm volatile("ldmatrix.sync.aligned.m8n8.x4.shared.b16 {%0,%1,%2,%3}, [%4];"
        : "=r"(r[0]), "=r"(r[1]), "=r"(r[2]), "=r"(r[3]) : "r"(addr));
}
__device__ __forceinline__ uint32_t smem_u32(const void* p) {
    uint32_t a;
    asm("{ .reg .u64 t; cvta.to.shared.u64 t, %1; cvt.u32.u64 %0, t; }"
        : "=r"(a) : "l"(p));
    return a;
}
__device__ __forceinline__ uint32_t pack_bf16x2(float a, float b) {
    __nv_bfloat16 x = __float2bfloat16(a), y = __float2bfloat16(b);
    return (uint32_t)__bfloat16_as_ushort(x)
         | ((uint32_t)__bfloat16_as_ushort(y) << 16);
}

// ===========================================================================
// Kernel S: exclusive prefix scan of lengths (1 CTA)
// ===========================================================================
__global__ void __launch_bounds__(512, 1) k_scan(const int* __restrict__ lengths)
{
    __shared__ int s[512];
    const int tid = threadIdx.x;
    const int base = tid * 8;
    int v[8]; int loc = 0;
    #pragma unroll
    for (int i = 0; i < 8; i++) { v[i] = lengths[base + i]; loc += v[i]; }
    s[tid] = loc;
    __syncthreads();
    for (int d = 1; d < 512; d <<= 1) {
        int t = (tid >= d) ? s[tid - d] : 0;
        __syncthreads();
        s[tid] += t;
        __syncthreads();
    }
    int run = s[tid] - loc;
    #pragma unroll
    for (int i = 0; i < 8; i++) { g_off_arr[base + i] = run; run += v[i]; }
    if (tid == 511) g_off_arr[BSZ] = s[511];
}

// ===========================================================================
// Kernel W1: split W_ih1 into bf16 hi/lo (gemm layout)
// ===========================================================================
__global__ void __launch_bounds__(256, 1) k_wsplit(const float* __restrict__ Wih1)
{
    int idx = blockIdx.x * 256 + threadIdx.x;
    if (idx < G4 * KP) {
        int n = idx / KP, k = idx % KP;
        float v = (k < HSZ) ? Wih1[n * HSZ + k] : 0.f;
        __nv_bfloat16 hi = __float2bfloat16(v);
        g_bhi[idx] = hi;
        g_blo[idx] = __float2bfloat16(v - __bfloat162float(hi));
    }
}

// ===========================================================================
// Kernel W2: Whh in pair-packed fragment layout (LDS.64-friendly)
//   j = ((n*7+kt)*32 + tg*8+g)*2 + sel ; sel=0 -> k=kt*16+2tg, sel=1 -> +8
// ===========================================================================
__global__ void __launch_bounds__(256, 1)
k_wprep(const float* __restrict__ W, uint32_t* __restrict__ dhi,
        uint32_t* __restrict__ dlo)
{
    int j = blockIdx.x * 256 + threadIdx.x;
    if (j >= W2N) return;
    int sel = j & 1;
    int pp  = (j >> 1) & 31;
    int tg  = pp >> 3, g = pp & 7;
    int grp = j >> 6;
    int kt  = grp % 7, n = grp / 7;
    int row = n * 8 + g;
    int gate = row / 104, u = row % 104;
    int k    = kt * 16 + 2 * tg + 8 * sel;
    float f0 = (u < HSZ && k     < HSZ) ? W[(gate * HSZ + u) * HSZ + k]     : 0.f;
    float f1 = (u < HSZ && k + 1 < HSZ) ? W[(gate * HSZ + u) * HSZ + k + 1] : 0.f;
    __nv_bfloat16 h0 = __float2bfloat16(f0), h1 = __float2bfloat16(f1);
    float r0 = f0 - __bfloat162float(h0), r1 = f1 - __bfloat162float(h1);
    dhi[j] = (uint32_t)__bfloat16_as_ushort(h0)
           | ((uint32_t)__bfloat16_as_ushort(h1) << 16);
    dlo[j] = pack_bf16x2(r0, r1);
}

// ===========================================================================
// Kernel Z0: g_z0pack = bias0 + x @ Wih0^T (packed rows)
// ===========================================================================
__global__ void __launch_bounds__(512, 1)
k_zx0(const float* __restrict__ x, const int* __restrict__ lengths,
      const float* __restrict__ Wih0,
      const float* __restrict__ bih0, const float* __restrict__ bhh0)
{
    __shared__ float sX[1400];
    __shared__ int sLen[32], sOff[32];
    const int tid = threadIdx.x;
    const int grow0 = blockIdx.x * 32;
    if (tid < 32) {
        sLen[tid] = lengths[grow0 + tid];
        sOff[tid] = g_off_arr[grow0 + tid];
    }
    const int u = tid;
    const bool act = (u < G4);
    unsigned long long wp[7];
    float b = 0.f;
    if (act) {
        float wr[14];
        #pragma unroll
        for (int k = 0; k < FSZ; k++) wr[k] = Wih0[u * FSZ + k];
        wr[13] = 0.f;
        #pragma unroll
        for (int i = 0; i < 7; i++) wp[i] = pk(wr[2*i], wr[2*i+1]);
        b = bih0[u] + bhh0[u];
    }
    __syncthreads();

    for (int r = 0; r < 32; r++) {
        const int len = sLen[r], off = sOff[r];
        __syncthreads();
        const float* xs = x + (size_t)(grow0 + r) * (TSZ * FSZ);
        for (int i = tid; i < 1400; i += 512) {
            int t = i / 14, k = i % 14;
            sX[i] = (k < FSZ) ? xs[t * FSZ + k] : 0.f;
        }
        __syncthreads();
        if (act) {
            for (int t = 0; t < len; t++) {
                unsigned long long acc = pk(b, 0.f);
                #pragma unroll
                for (int kp = 0; kp < 7; kp++)
                    ffma2(acc, wp[kp], *(const unsigned long long*)&sX[t*14 + 2*kp]);
                g_z0pack[(size_t)(off + t) * G4 + u] = psum(acc);
            }
        }
    }
}

// ===========================================================================
// Kernel R: tensor-core recurrent LSTM layer (MODE 0: layer0, 1: layer1+fc)
// ===========================================================================
template<int MODE>
__global__ void __launch_bounds__(RTH, 1)
k_rec(const int* __restrict__ lengths,
      const float* __restrict__ Wfc, const float* __restrict__ bfc,
      float* __restrict__ out)
{
    extern __shared__ char smc[];
    uint32_t* sWhi = (uint32_t*)(smc);                   // 93184 B
    uint32_t* sWlo = (uint32_t*)(smc + 93184);           // 93184 B
    uint32_t* sHhi = (uint32_t*)(smc + 186368);          // 17408 B (2 bufs)
    uint32_t* sHlo = (uint32_t*)(smc + 203776);          // 17408 B
    int*   sLen = (int*)(smc + 221184);
    int*   sOff = (int*)(smc + 221312);
    float* sWf  = (float*)(smc + 221440);
    float* sHF  = (float*)(smc);                         // fc reuse

    const uint32_t* gwhi = MODE ? g_w2hi1 : g_w2hi0;
    const uint32_t* gwlo = MODE ? g_w2lo1 : g_w2lo0;
    const float*    zsrc = MODE ? g_zpack : g_z0pack;

    const int tid = threadIdx.x;
    const int grow0 = blockIdx.x * 32;

    for (int i = tid; i < W2N; i += RTH) { sWhi[i] = gwhi[i]; sWlo[i] = gwlo[i]; }
    for (int i = tid; i < 2 * HBUFW; i += RTH) { sHhi[i] = 0u; sHlo[i] = 0u; }
    if (tid < 32) {
        sLen[tid] = lengths[grow0 + tid];
        sOff[tid] = g_off_arr[grow0 + tid];
    }
    if (MODE == 1 && tid < HSZ) sWf[tid] = Wfc[tid];
    __syncthreads();

    int Lmax = 0;
    #pragma unroll
    for (int r = 0; r < 32; r++) Lmax = max(Lmax, sLen[r]);

    const int w = tid >> 5, lane = tid & 31;
    const int g = lane >> 2, tg = lane & 3;
    const int u0 = w * 8 + 2 * tg;
    const bool cv = (u0 < HSZ);

    const uint32_t sb = smem_u32(smc);
    const uint32_t lmoff = ((lane & 15) * HROW + (lane >> 4) * 4) * 4;
    const uint32_t hHiB = sb + 186368 + lmoff;
    const uint32_t hLoB = sb + 203776 + lmoff;

    int rown[4], lenr[4], offr[4];
    #pragma unroll
    for (int ri = 0; ri < 4; ri++) {
        int mt = ri >> 1, rh = ri & 1;
        rown[ri] = mt * 16 + rh * 8 + g;
        lenr[ri] = sLen[rown[ri]];
        offr[ri] = sOff[rown[ri]];
    }
    float c[4][2] = {{0.f,0.f},{0.f,0.f},{0.f,0.f},{0.f,0.f}};
    float h[4][2] = {{0.f,0.f},{0.f,0.f},{0.f,0.f},{0.f,0.f}};

    int p = 0;
    #pragma unroll 1
    for (int t = 0; t < Lmax; t++) {
        // z(t) prefetch as float2 (hidden under the MMA block)
        float2 zn[4][4];
        #pragma unroll
        for (int ri = 0; ri < 4; ri++) {
            const bool lv = cv && (t < lenr[ri]);
            const size_t zb = (size_t)(offr[ri] + t) * G4;
            #pragma unroll
            for (int G = 0; G < 4; G++)
                zn[ri][G] = lv ? *(const float2*)&zsrc[zb + G * HSZ + u0]
                               : make_float2(0.f, 0.f);
        }

        float D[2][4][4];
        #pragma unroll
        for (int mt = 0; mt < 2; mt++)
            #pragma unroll
            for (int G = 0; G < 4; G++)
                #pragma unroll
                for (int q = 0; q < 4; q++) D[mt][G][q] = 0.f;

        const uint32_t hHi = hHiB + p * (HBUFW * 4);
        const uint32_t hLo = hLoB + p * (HBUFW * 4);
        #pragma unroll
        for (int kt = 0; kt < 7; kt++) {
            uint32_t ahi[2][4], alo[2][4];
            #pragma unroll
            for (int mt = 0; mt < 2; mt++) {
                const uint32_t off = (mt * 16 * HROW + kt * 8) * 4;
                ldsm4(ahi[mt], hHi + off);
                ldsm4(alo[mt], hLo + off);
            }
            #pragma unroll
            for (int G = 0; G < 4; G++) {
                const int b2 = (((G * 13 + w) * 7 + kt) * 32 + tg * 8 + g) * 2;
                uint2 bh = *(const uint2*)&sWhi[b2];
                uint2 bl = *(const uint2*)&sWlo[b2];
                #pragma unroll
                for (int mt = 0; mt < 2; mt++) {
                    mma_bf16(D[mt][G], ahi[mt], bh.x, bh.y);
                    mma_bf16(D[mt][G], alo[mt], bh.x, bh.y);
                    mma_bf16(D[mt][G], ahi[mt], bl.x, bl.y);
                }
            }
        }

        // activation + state update + stage h(t+1)
        uint32_t* Nh = sHhi + (1 - p) * HBUFW;
        uint32_t* Nl = sHlo + (1 - p) * HBUFW;
        #pragma unroll
        for (int ri = 0; ri < 4; ri++) {
            const int mt = ri >> 1, rh = ri & 1;
            const bool upd = cv && (t < lenr[ri]);
            #pragma unroll
            for (int j = 0; j < 2; j++) {
                float zi = D[mt][0][rh * 2 + j] + (j ? zn[ri][0].y : zn[ri][0].x);
                float zf = D[mt][1][rh * 2 + j] + (j ? zn[ri][1].y : zn[ri][1].x);
                float zg = D[mt][2][rh * 2 + j] + (j ? zn[ri][2].y : zn[ri][2].x);
                float zo = D[mt][3][rh * 2 + j] + (j ? zn[ri][3].y : zn[ri][3].x);
                float cn = sigf(zf) * c[ri][j] + siga(zi) * tanha(zg);
                float hn = siga(zo) * tanha(cn);
                if (upd) { c[ri][j] = cn; h[ri][j] = hn; }
            }
            __nv_bfloat16 b0 = __float2bfloat16(h[ri][0]);
            __nv_bfloat16 b1 = __float2bfloat16(h[ri][1]);
            float l0 = h[ri][0] - __bfloat162float(b0);
            float l1 = h[ri][1] - __bfloat162float(b1);
            uint32_t hw = (uint32_t)__bfloat16_as_ushort(b0)
                        | ((uint32_t)__bfloat16_as_ushort(b1) << 16);
            uint32_t lw = pack_bf16x2(l0, l1);
            const int word = rown[ri] * HROW + w * 4 + tg;
            Nh[word] = hw; Nl[word] = lw;
            if (MODE == 0 && upd) {
                size_t o = ((size_t)offr[ri] + t) * HSZ + u0;
                *(uint32_t*)&g_h0hi[o] = hw;
                *(uint32_t*)&g_h0lo[o] = lw;
            }
        }
        __syncthreads();
        p ^= 1;
    }

    if (MODE == 1) {
        #pragma unroll
        for (int ri = 0; ri < 4; ri++) {
            if (cv) {
                sHF[rown[ri] * HSZ + u0]     = h[ri][0];
                sHF[rown[ri] * HSZ + u0 + 1] = h[ri][1];
            }
        }
        __syncthreads();
        if (tid < 32) {
            float s = bfc[0];
            #pragma unroll 10
            for (int k = 0; k < HSZ; k++) s += sHF[tid * HSZ + k] * sWf[k];
            out[grow0 + tid] = s;
        }
    }
}

// ===========================================================================
// Kernel G: zpack = h0pack @ Wih1^T + bias1 (merged split terms + ldmatrix A)
// ===========================================================================
__global__ void __launch_bounds__(512, 1)
k_gemm_mma(const float* __restrict__ bih1, const float* __restrict__ bhh1)
{
    extern __shared__ char smc[];
    float*          sBias = (float*)smc;
    __nv_bfloat16*  sAhi  = (__nv_bfloat16*)(smc + 1600);
    __nv_bfloat16*  sAlo  = (__nv_bfloat16*)(smc + 32320);
    __nv_bfloat16*  sBhi  = (__nv_bfloat16*)(smc + 63040);
    __nv_bfloat16*  sBlo  = (__nv_bfloat16*)(smc + 116800);

    const int tid  = threadIdx.x;
    const int wid  = tid >> 5, lane = tid & 31;
    const int g    = lane >> 2, tg = lane & 3;
    const int wm   = (wid & 3) * 32;
    const int wn   = (wid >> 2) * 56;

    for (int i = tid; i < G4; i += 512) sBias[i] = bih1[i] + bhh1[i];
    for (int i = tid; i < 128 * 20; i += 512) {
        int r = i / 20, kk = 100 + i % 20;
        sAhi[r * LDA + kk] = __float2bfloat16(0.f);
        sAlo[r * LDA + kk] = __float2bfloat16(0.f);
    }
    for (int i = tid; i < 24 * LDB; i += 512) {
        int r = 200 + i / LDB, kk = i % LDB;
        sBhi[r * LDB + kk] = __float2bfloat16(0.f);
        sBlo[r * LDB + kk] = __float2bfloat16(0.f);
    }

    const uint32_t aHiB = smem_u32(sAhi) + ((lane & 15) * (LDA/2) + (lane >> 4) * 4) * 4;
    const uint32_t aLoB = smem_u32(sAlo) + ((lane & 15) * (LDA/2) + (lane >> 4) * 4) * 4;

    const int Mpack  = g_off_arr[BSZ];
    const int ntiles = (Mpack + 127) >> 7;
    const int nitems = ntiles * 2;
    int curHalf = -1;

    #pragma unroll 1
    for (int it = blockIdx.x; it < nitems; it += gridDim.x) {
        const int half  = (it >= ntiles) ? 1 : 0;
        const int mtile = it - half * ntiles;
        const size_t m0 = (size_t)mtile << 7;
        const int jo    = half * 200;

        __syncthreads();
        if (half != curHalf) {
            curHalf = half;
            #pragma unroll 1
            for (int i = tid; i < 200 * 14; i += 512) {
                int n = i / 14, kc = (i % 14) * 8;
                size_t go = (size_t)(jo + n) * KP + kc;
                *(uint4*)&sBhi[n * LDB + kc] = *(const uint4*)&g_bhi[go];
                *(uint4*)&sBlo[n * LDB + kc] = *(const uint4*)&g_blo[go];
            }
        }
        #pragma unroll 1
        for (int i = tid; i < 128 * 25; i += 512) {
            int r = i / 25, kc = (i % 25) * 4;
            size_t go = (m0 + r) * HSZ + kc;
            *(uint2*)&sAhi[r * LDA + kc] = *(const uint2*)&g_h0hi[go];
            *(uint2*)&sAlo[r * LDA + kc] = *(const uint2*)&g_h0lo[go];
        }
        __syncthreads();

        float D[2][7][4];
        #pragma unroll
        for (int mt = 0; mt < 2; mt++)
            #pragma unroll
            for (int nt = 0; nt < 7; nt++)
                #pragma unroll
                for (int q = 0; q < 4; q++) D[mt][nt][q] = 0.f;

        #pragma unroll
        for (int ks = 0; ks < 7; ks++) {
            uint32_t ahi[2][4], alo[2][4];
            #pragma unroll
            for (int mt = 0; mt < 2; mt++) {
                const uint32_t off = ((wm + mt * 16) * (LDA/2) + ks * 8) * 4;
                ldsm4(ahi[mt], aHiB + off);
                ldsm4(alo[mt], aLoB + off);
            }
            const int kb = ks * 16;
            #pragma unroll
            for (int nt = 0; nt < 7; nt++) {
                const int brow = (wn + nt * 8 + g) * LDB + kb + 2 * tg;
                uint32_t bh0 = *(const uint32_t*)&sBhi[brow];
                uint32_t bh1 = *(const uint32_t*)&sBhi[brow + 8];
                uint32_t bl0 = *(const uint32_t*)&sBlo[brow];
                uint32_t bl1 = *(const uint32_t*)&sBlo[brow + 8];
                #pragma unroll
                for (int mt = 0; mt < 2; mt++) {
                    mma_bf16(D[mt][nt], ahi[mt], bh0, bh1);
                    mma_bf16(D[mt][nt], alo[mt], bh0, bh1);
                    mma_bf16(D[mt][nt], ahi[mt], bl0, bl1);
                }
            }
        }

        #pragma unroll
        for (int mt = 0; mt < 2; mt++) {
            #pragma unroll
            for (int nt = 0; nt < 7; nt++) {
                int n_rel = wn + nt * 8 + 2 * tg;
                if (n_rel < 200) {
                    int ncol = jo + n_rel;
                    float b0v = sBias[ncol], b1v = sBias[ncol + 1];
                    size_t R = m0 + wm + mt * 16 + g;
                    if (R < (size_t)Mpack) {
                        float2 v = make_float2(D[mt][nt][0] + b0v, D[mt][nt][1] + b1v);
                        *(float2*)&g_zpack[R * G4 + ncol] = v;
                    }
                    if (R + 8 < (size_t)Mpack) {
                        float2 v = make_float2(D[mt][nt][2] + b0v, D[mt][nt][3] + b1v);
                        *(float2*)&g_zpack[(R + 8) * G4 + ncol] = v;
                    }
                }
            }
        }
    }
}

// ===========================================================================
// Launch
// ===========================================================================
extern "C" void kernel_launch(void* const* d_in, const int* in_sizes, int n_in,
                              void* d_out, int out_size)
{
    const float* x       = (const float*)d_in[0];
    const int*   lengths = (const int*)  d_in[1];
    const float* Wih0    = (const float*)d_in[2];
    const float* Whh0    = (const float*)d_in[3];
    const float* bih0    = (const float*)d_in[4];
    const float* bhh0    = (const float*)d_in[5];
    const float* Wih1    = (const float*)d_in[6];
    const float* Whh1    = (const float*)d_in[7];
    const float* bih1    = (const float*)d_in[8];
    const float* bhh1    = (const float*)d_in[9];
    const float* Wfc     = (const float*)d_in[10];
    const float* bfc     = (const float*)d_in[11];
    float* out = (float*)d_out;

    uint32_t *w2hi0, *w2lo0, *w2hi1, *w2lo1;
    cudaGetSymbolAddress((void**)&w2hi0, g_w2hi0);
    cudaGetSymbolAddress((void**)&w2lo0, g_w2lo0);
    cudaGetSymbolAddress((void**)&w2hi1, g_w2hi1);
    cudaGetSymbolAddress((void**)&w2lo1, g_w2lo1);

    const int smG = 1600 + 2 * 30720 + 2 * 53760;   // 170,560
    const int smR = 221952;

    cudaFuncSetAttribute(k_gemm_mma, cudaFuncAttributeMaxDynamicSharedMemorySize, smG);
    cudaFuncSetAttribute(k_rec<0>,   cudaFuncAttributeMaxDynamicSharedMemorySize, smR);
    cudaFuncSetAttribute(k_rec<1>,   cudaFuncAttributeMaxDynamicSharedMemorySize, smR);

    k_scan  <<<1, 512>>>(lengths);
    k_wsplit<<<(G4 * KP + 255) / 256, 256>>>(Wih1);
    k_wprep <<<(W2N + 255) / 256, 256>>>(Whh0, w2hi0, w2lo0);
    k_wprep <<<(W2N + 255) / 256, 256>>>(Whh1, w2hi1, w2lo1);
    k_zx0   <<<128, 512>>>(x, lengths, Wih0, bih0, bhh0);
    k_rec<0><<<128, RTH, smR>>>(lengths, nullptr, nullptr, nullptr);
    k_gemm_mma<<<148, 512, smG>>>(bih1, bhh1);
    k_rec<1><<<128, RTH, smR>>>(lengths, Wfc, bfc, out);
}